// round 4
// baseline (speedup 1.0000x reference)
#include <cuda_runtime.h>
#include <math.h>

#define BATCH 2
#define SEQ   2048
#define EMBED 1024
#define HEADS 16
#define HDIM  64
#define MLPD  4096
#define ROWS  (BATCH*SEQ)          // 4096
#define NEG_INF (-1e30f)

// ---------------- scratch (device globals; zero-init BSS; 16B-aligned) ----
__device__ __align__(16) float g_shift[BATCH*EMBED];
__device__ __align__(16) float g_scale[BATCH*EMBED];
__device__ __align__(16) float g_xa  [ROWS*EMBED];        // adaln output
__device__ __align__(16) float g_qkv [ROWS*3*EMBED];      // qkv gemm out
__device__ __align__(16) float g_attn[ROWS*EMBED];        // attention out (pre-proj)
__device__ __align__(16) float g_x1  [ROWS*EMBED];        // x + attn branch
__device__ __align__(16) float g_h   [ROWS*2*MLPD];       // mlp1 out
__device__ __align__(16) float g_hg  [ROWS*MLPD];         // swiglu out

// ---------------- adaLN modulation vectors -> g_shift / g_scale -----------
__global__ void modvec_kernel(const float* __restrict__ c,
                              const float* __restrict__ shift_w, const float* __restrict__ shift_b,
                              const float* __restrict__ scale_w, const float* __restrict__ scale_b) {
    int gw   = (blockIdx.x * blockDim.x + threadIdx.x) >> 5;   // 0..4095
    int lane = threadIdx.x & 31;
    int which = gw >> 11;            // 0=shift, 1=scale
    int b     = (gw >> 10) & 1;
    int j     = gw & 1023;
    const float* w  = (which ? scale_w : shift_w) + (size_t)j * EMBED;
    const float* cb = c + b * EMBED;
    float acc = 0.f;
    for (int k = lane; k < EMBED; k += 32) {
        float cv = cb[k];
        float s  = cv / (1.f + expf(-cv));
        acc += s * w[k];
    }
    #pragma unroll
    for (int off = 16; off; off >>= 1) acc += __shfl_xor_sync(0xffffffffu, acc, off);
    if (lane == 0) {
        if (which == 0) g_shift[b*EMBED + j] = acc + shift_b[j];
        else {
            float v = acc + scale_b[j] + 1.0f;
            g_scale[b*EMBED + j] = fminf(fmaxf(v, 0.1f), 10.0f);
        }
    }
}

// ---------------- RMS-like norm + modulate; SRC=0: param x, SRC=1: g_x1 ---
template<int SRC>
__global__ void adaln_kernel(const float* __restrict__ xext, const float* __restrict__ norm_w) {
    int row = blockIdx.x;               // 0..4095
    int b   = row >> 11;
    const float* xp = (SRC == 0) ? xext : g_x1;
    const float4* xr = (const float4*)(xp + (size_t)row * EMBED);
    float4 v = xr[threadIdx.x];
    float ss = v.x*v.x + v.y*v.y + v.z*v.z + v.w*v.w;
    __shared__ float red[8];
    #pragma unroll
    for (int off = 16; off; off >>= 1) ss += __shfl_xor_sync(0xffffffffu, ss, off);
    if ((threadIdx.x & 31) == 0) red[threadIdx.x >> 5] = ss;
    __syncthreads();
    __shared__ float s_inv;
    if (threadIdx.x == 0) {
        float t = 0.f;
        #pragma unroll
        for (int i = 0; i < 8; i++) t += red[i];
        float nrm = sqrtf(t) * (1.f / 32.f);       // ||x|| * C^-0.5
        s_inv = 1.f / fmaxf(nrm, 1e-6f);
    }
    __syncthreads();
    float inv = s_inv;
    const float4 nw = ((const float4*)norm_w)[threadIdx.x];
    const float4 sc = ((const float4*)(g_scale + (size_t)b*EMBED))[threadIdx.x];
    const float4 sh = ((const float4*)(g_shift + (size_t)b*EMBED))[threadIdx.x];
    float4 o;
    o.x = v.x * inv * nw.x * sc.x + sh.x;
    o.y = v.y * inv * nw.y * sc.y + sh.y;
    o.z = v.z * inv * nw.z * sc.z + sh.z;
    o.w = v.w * inv * nw.w * sc.w + sh.w;
    ((float4*)(g_xa + (size_t)row * EMBED))[threadIdx.x] = o;
}

// ---------------- tiled SGEMM: C[m][n] = sum_k A[m][k]*W[n][k] (+bias)(+res)
// ASEL: 0=g_xa 1=g_attn 2=g_hg ; CSEL: 0=g_qkv 1=g_x1 2=g_h 3=param
// RESX: residual from param resx ; RESG: residual from g_x1
template<int ASEL, int CSEL, bool BIAS, bool RESX, bool RESG>
__global__ __launch_bounds__(256)
void sgemm_kernel(const float* __restrict__ W, const float* __restrict__ bias,
                  const float* __restrict__ resx, float* __restrict__ Cext,
                  int M, int Nn, int K) {
    const float* A = (ASEL == 0) ? g_xa : (ASEL == 1) ? g_attn : g_hg;
    float*       C = (CSEL == 0) ? g_qkv : (CSEL == 1) ? g_x1 : (CSEL == 2) ? g_h : Cext;

    __shared__ __align__(16) float As[8][128];
    __shared__ __align__(16) float Ws[8][128];
    int tid = threadIdx.x;
    int tx = tid & 15, ty = tid >> 4;
    int bm = blockIdx.y * 128, bn = blockIdx.x * 128;

    float acc[8][8];
    #pragma unroll
    for (int i = 0; i < 8; i++)
        #pragma unroll
        for (int j = 0; j < 8; j++) acc[i][j] = 0.f;

    int lrow = tid >> 1;
    int lcol = (tid & 1) * 4;
    const float* Ag = A + (size_t)(bm + lrow) * K + lcol;
    const float* Wg = W + (size_t)(bn + lrow) * K + lcol;

    for (int k0 = 0; k0 < K; k0 += 8) {
        float4 av = *(const float4*)(Ag + k0);
        float4 wv = *(const float4*)(Wg + k0);
        As[lcol+0][lrow] = av.x; As[lcol+1][lrow] = av.y;
        As[lcol+2][lrow] = av.z; As[lcol+3][lrow] = av.w;
        Ws[lcol+0][lrow] = wv.x; Ws[lcol+1][lrow] = wv.y;
        Ws[lcol+2][lrow] = wv.z; Ws[lcol+3][lrow] = wv.w;
        __syncthreads();
        #pragma unroll
        for (int k = 0; k < 8; k++) {
            float4 a0 = *(const float4*)&As[k][ty*4];
            float4 a1 = *(const float4*)&As[k][ty*4 + 64];
            float4 b0 = *(const float4*)&Ws[k][tx*4];
            float4 b1 = *(const float4*)&Ws[k][tx*4 + 64];
            float a[8] = {a0.x,a0.y,a0.z,a0.w, a1.x,a1.y,a1.z,a1.w};
            float bb[8] = {b0.x,b0.y,b0.z,b0.w, b1.x,b1.y,b1.z,b1.w};
            #pragma unroll
            for (int i = 0; i < 8; i++)
                #pragma unroll
                for (int j = 0; j < 8; j++)
                    acc[i][j] = fmaf(a[i], bb[j], acc[i][j]);
        }
        __syncthreads();
    }
    #pragma unroll
    for (int i = 0; i < 8; i++) {
        int r = bm + ((i < 4) ? (ty*4 + i) : (64 + ty*4 + i - 4));
        #pragma unroll
        for (int j = 0; j < 8; j++) {
            int cc = bn + ((j < 4) ? (tx*4 + j) : (64 + tx*4 + j - 4));
            float v = acc[i][j];
            if (BIAS) v += bias[cc];
            if (RESX) v += resx[(size_t)r * Nn + cc];
            if (RESG) v += g_x1[(size_t)r * Nn + cc];
            C[(size_t)r * Nn + cc] = v;
        }
    }
}

// ---------------- flash attention (32 queries x 64-key tiles, D=64) -------
// grid: (SEQ/32, HEADS, BATCH), block 256 (16x16). Reads g_qkv, writes g_attn.
__global__ __launch_bounds__(256)
void attn_kernel(const int* __restrict__ mask) {
    __shared__ __align__(16) float qs[32*65];
    __shared__ __align__(16) float ks[64*65];   // reused for P tile
    __shared__ __align__(16) float vs[64*64];
    __shared__ int msk[64];

    int tid = threadIdx.x;
    int tx = tid & 15, ty = tid >> 4;
    int qt = blockIdx.x, h = blockIdx.y, b = blockIdx.z;
    int q0 = qt * 32;

    for (int i = tid; i < 512; i += 256) {
        int r = i >> 4, c4 = (i & 15) * 4;
        float4 v = *(const float4*)(g_qkv + (size_t)(b*SEQ + q0 + r) * 3072 + h*HDIM + c4);
        qs[r*65 + c4+0] = v.x; qs[r*65 + c4+1] = v.y;
        qs[r*65 + c4+2] = v.z; qs[r*65 + c4+3] = v.w;
    }

    float m[2], l[2], acc[2][4];
    #pragma unroll
    for (int i = 0; i < 2; i++) {
        m[i] = NEG_INF; l[i] = 0.f;
        #pragma unroll
        for (int j = 0; j < 4; j++) acc[i][j] = 0.f;
    }

    for (int kt = 0; kt < SEQ/64; kt++) {
        __syncthreads();
        for (int i = tid; i < 1024; i += 256) {
            int r = i >> 4, c4 = (i & 15) * 4;
            const float* base = g_qkv + (size_t)(b*SEQ + kt*64 + r) * 3072 + h*HDIM;
            float4 kv = *(const float4*)(base + 1024 + c4);
            float4 vv = *(const float4*)(base + 2048 + c4);
            ks[r*65 + c4+0] = kv.x; ks[r*65 + c4+1] = kv.y;
            ks[r*65 + c4+2] = kv.z; ks[r*65 + c4+3] = kv.w;
            vs[r*64 + c4+0] = vv.x; vs[r*64 + c4+1] = vv.y;
            vs[r*64 + c4+2] = vv.z; vs[r*64 + c4+3] = vv.w;
        }
        if (tid < 64) msk[tid] = mask[b*SEQ + kt*64 + tid];
        __syncthreads();

        float s[2][4];
        #pragma unroll
        for (int i = 0; i < 2; i++)
            #pragma unroll
            for (int j = 0; j < 4; j++) s[i][j] = 0.f;
        #pragma unroll 8
        for (int d = 0; d < 64; d++) {
            float aq[2], bk[4];
            #pragma unroll
            for (int i = 0; i < 2; i++) aq[i] = qs[(ty*2+i)*65 + d];
            #pragma unroll
            for (int j = 0; j < 4; j++) bk[j] = ks[(tx*4+j)*65 + d];
            #pragma unroll
            for (int i = 0; i < 2; i++)
                #pragma unroll
                for (int j = 0; j < 4; j++) s[i][j] = fmaf(aq[i], bk[j], s[i][j]);
        }

        #pragma unroll
        for (int i = 0; i < 2; i++) {
            float tmax = NEG_INF;
            #pragma unroll
            for (int j = 0; j < 4; j++) {
                s[i][j] = msk[tx*4+j] ? s[i][j] * 0.125f : NEG_INF;
                tmax = fmaxf(tmax, s[i][j]);
            }
            #pragma unroll
            for (int off = 8; off; off >>= 1)
                tmax = fmaxf(tmax, __shfl_xor_sync(0xffffffffu, tmax, off, 16));
            float mnew = fmaxf(m[i], tmax);
            float alpha, psum = 0.f;
            if (mnew <= NEG_INF) {
                alpha = 1.f;
                #pragma unroll
                for (int j = 0; j < 4; j++) s[i][j] = 0.f;
            } else {
                alpha = expf(m[i] - mnew);
                #pragma unroll
                for (int j = 0; j < 4; j++) {
                    float p = expf(s[i][j] - mnew);
                    s[i][j] = p; psum += p;
                }
            }
            #pragma unroll
            for (int off = 8; off; off >>= 1)
                psum += __shfl_xor_sync(0xffffffffu, psum, off, 16);
            l[i] = l[i] * alpha + psum;
            m[i] = mnew;
            #pragma unroll
            for (int d = 0; d < 4; d++) acc[i][d] *= alpha;
        }

        __syncthreads();
        #pragma unroll
        for (int i = 0; i < 2; i++)
            #pragma unroll
            for (int j = 0; j < 4; j++)
                ks[(ty*2+i)*65 + tx*4+j] = s[i][j];     // P tile (32x64)
        __syncthreads();

        #pragma unroll 8
        for (int j = 0; j < 64; j++) {
            float ap[2];
            #pragma unroll
            for (int i = 0; i < 2; i++) ap[i] = ks[(ty*2+i)*65 + j];
            float4 vv = *(const float4*)&vs[j*64 + tx*4];
            #pragma unroll
            for (int i = 0; i < 2; i++) {
                acc[i][0] = fmaf(ap[i], vv.x, acc[i][0]);
                acc[i][1] = fmaf(ap[i], vv.y, acc[i][1]);
                acc[i][2] = fmaf(ap[i], vv.z, acc[i][2]);
                acc[i][3] = fmaf(ap[i], vv.w, acc[i][3]);
            }
        }
    }

    #pragma unroll
    for (int i = 0; i < 2; i++) {
        float invl = (l[i] > 0.f) ? (1.f / l[i]) : 0.f;
        int t = q0 + ty*2 + i;
        float4 o = make_float4(acc[i][0]*invl, acc[i][1]*invl, acc[i][2]*invl, acc[i][3]*invl);
        *(float4*)(g_attn + (size_t)(b*SEQ + t) * EMBED + h*HDIM + tx*4) = o;
    }
}

// ---------------- swiglu: g_hg = silu(g_h[:, :MLPD]) * g_h[:, MLPD:] ------
__global__ void swiglu_kernel() {
    int idx = blockIdx.x * blockDim.x + threadIdx.x;   // over ROWS*MLPD/4 float4s
    int row = idx >> 10;
    int c4  = (idx & 1023) * 4;
    const float* base = g_h + (size_t)row * (2*MLPD);
    float4 a = *(const float4*)(base + c4);
    float4 g = *(const float4*)(base + MLPD + c4);
    float4 o;
    o.x = a.x / (1.f + expf(-a.x)) * g.x;
    o.y = a.y / (1.f + expf(-a.y)) * g.y;
    o.z = a.z / (1.f + expf(-a.z)) * g.z;
    o.w = a.w / (1.f + expf(-a.w)) * g.w;
    *(float4*)(g_hg + (size_t)row * MLPD + c4) = o;
}

// ------------------------------ launch ------------------------------------
static const int SIG_DECL[15] = {4194304,2048,4096,1024,1048576,1024,1048576,1024,
                                3145728,1048576,1024,8388608,8192,4194304,1024};
static const int SIG_ALPHA[15] = {4096,2048,8192,1024,8388608,4194304,1024,1024,
                                  1048576,3145728,1024,1048576,1024,1048576,4194304};
static const int MAP_ALPHA[15] = {14,1,0,6,11,10,13,12,9,8,7,4,2,5,3};

extern "C" void kernel_launch(void* const* d_in, const int* in_sizes, int n_in,
                              void* d_out, int out_size) {
    const void* in[15];
    bool decl_ok = (n_in >= 15), alpha_ok = (n_in >= 15);
    for (int i = 0; i < 15 && i < n_in; i++) {
        if (in_sizes[i] != SIG_DECL[i])  decl_ok = false;
        if (in_sizes[i] != SIG_ALPHA[i]) alpha_ok = false;
    }
    if (!decl_ok && alpha_ok) {
        for (int r = 0; r < 15; r++) in[r] = d_in[MAP_ALPHA[r]];
    } else {
        for (int r = 0; r < 15; r++) in[r] = d_in[r];
    }

    const float* x      = (const float*)in[0];
    const float* c      = (const float*)in[1];
    const int*   amask  = (const int*)  in[2];
    const float* norm_w = (const float*)in[3];
    const float* scale_w= (const float*)in[4];
    const float* scale_b= (const float*)in[5];
    const float* shift_w= (const float*)in[6];
    const float* shift_b= (const float*)in[7];
    const float* qkv_w  = (const float*)in[8];
    const float* proj_w = (const float*)in[9];
    const float* proj_b = (const float*)in[10];
    const float* mlp_w1 = (const float*)in[11];
    const float* mlp_b1 = (const float*)in[12];
    const float* mlp_w2 = (const float*)in[13];
    const float* mlp_b2 = (const float*)in[14];
    float* out = (float*)d_out;

    // 1) adaLN modulation vectors (shared by both adaLN calls)
    modvec_kernel<<<512, 256>>>(c, shift_w, shift_b, scale_w, scale_b);
    // 2) g_xa = adaLN(x)
    adaln_kernel<0><<<ROWS, 256>>>(x, norm_w);
    // 3) g_qkv = g_xa @ qkv_w.T
    sgemm_kernel<0,0,false,false,false><<<dim3(3*EMBED/128, ROWS/128), 256>>>(
        qkv_w, nullptr, nullptr, nullptr, ROWS, 3*EMBED, EMBED);
    // 4) g_attn = flashattn(g_qkv)
    attn_kernel<<<dim3(SEQ/32, HEADS, BATCH), 256>>>(amask);
    // 5) g_x1 = x + g_attn @ proj_w.T + proj_b
    sgemm_kernel<1,1,true,true,false><<<dim3(EMBED/128, ROWS/128), 256>>>(
        proj_w, proj_b, x, nullptr, ROWS, EMBED, EMBED);
    // 6) g_xa = adaLN(g_x1)
    adaln_kernel<1><<<ROWS, 256>>>(nullptr, norm_w);
    // 7) g_h = g_xa @ mlp_w1.T + mlp_b1
    sgemm_kernel<0,2,true,false,false><<<dim3(2*MLPD/128, ROWS/128), 256>>>(
        mlp_w1, mlp_b1, nullptr, nullptr, ROWS, 2*MLPD, EMBED);
    // 8) g_hg = swiglu(g_h)
    swiglu_kernel<<<ROWS*(MLPD/4)/256, 256>>>();
    // 9) out = g_x1 + g_hg @ mlp_w2.T + mlp_b2
    sgemm_kernel<2,3,true,false,true><<<dim3(EMBED/128, ROWS/128), 256>>>(
        mlp_w2, mlp_b2, nullptr, out, ROWS, EMBED, MLPD);
}

// round 6
// speedup vs baseline: 2.8774x; 2.8774x over previous
#include <cuda_runtime.h>
#include <math.h>

#define BATCH 2
#define SEQ   2048
#define EMBED 1024
#define HEADS 16
#define HDIM  64
#define MLPD  4096
#define ROWS  (BATCH*SEQ)          // 4096
#define NEG_INF (-1e30f)

// ---------------- scratch (device globals; zero-init BSS; 16B-aligned) ----
__device__ __align__(16) float g_shift[BATCH*EMBED];
__device__ __align__(16) float g_scale[BATCH*EMBED];
__device__ __align__(16) float g_xa  [ROWS*EMBED];        // adaln output
__device__ __align__(16) float g_qkv [ROWS*3*EMBED];      // qkv gemm out
__device__ __align__(16) float g_attn[ROWS*EMBED];        // attention out (pre-proj)
__device__ __align__(16) float g_x1  [ROWS*EMBED];        // x + attn branch
__device__ __align__(16) float g_h   [ROWS*2*MLPD];       // mlp1 out
__device__ __align__(16) float g_hg  [ROWS*MLPD];         // swiglu out

__device__ __forceinline__ unsigned f2tf32(float f) {
    unsigned r;
    asm("cvt.rna.tf32.f32 %0, %1;" : "=r"(r) : "f"(f));
    return r;
}

// ---------------- adaLN modulation vectors -> g_shift / g_scale -----------
__global__ void modvec_kernel(const float* __restrict__ c,
                              const float* __restrict__ shift_w, const float* __restrict__ shift_b,
                              const float* __restrict__ scale_w, const float* __restrict__ scale_b) {
    int gw   = (blockIdx.x * blockDim.x + threadIdx.x) >> 5;   // 0..4095
    int lane = threadIdx.x & 31;
    int which = gw >> 11;            // 0=shift, 1=scale
    int b     = (gw >> 10) & 1;
    int j     = gw & 1023;
    const float* w  = (which ? scale_w : shift_w) + (size_t)j * EMBED;
    const float* cb = c + b * EMBED;
    float acc = 0.f;
    for (int k = lane; k < EMBED; k += 32) {
        float cv = cb[k];
        float s  = cv / (1.f + expf(-cv));
        acc += s * w[k];
    }
    #pragma unroll
    for (int off = 16; off; off >>= 1) acc += __shfl_xor_sync(0xffffffffu, acc, off);
    if (lane == 0) {
        if (which == 0) g_shift[b*EMBED + j] = acc + shift_b[j];
        else {
            float v = acc + scale_b[j] + 1.0f;
            g_scale[b*EMBED + j] = fminf(fmaxf(v, 0.1f), 10.0f);
        }
    }
}

// ---------------- RMS-like norm + modulate; SRC=0: param x, SRC=1: g_x1 ---
template<int SRC>
__global__ void adaln_kernel(const float* __restrict__ xext, const float* __restrict__ norm_w) {
    int row = blockIdx.x;               // 0..4095
    int b   = row >> 11;
    const float* xp = (SRC == 0) ? xext : g_x1;
    const float4* xr = (const float4*)(xp + (size_t)row * EMBED);
    float4 v = xr[threadIdx.x];
    float ss = v.x*v.x + v.y*v.y + v.z*v.z + v.w*v.w;
    __shared__ float red[8];
    #pragma unroll
    for (int off = 16; off; off >>= 1) ss += __shfl_xor_sync(0xffffffffu, ss, off);
    if ((threadIdx.x & 31) == 0) red[threadIdx.x >> 5] = ss;
    __syncthreads();
    __shared__ float s_inv;
    if (threadIdx.x == 0) {
        float t = 0.f;
        #pragma unroll
        for (int i = 0; i < 8; i++) t += red[i];
        float nrm = sqrtf(t) * (1.f / 32.f);       // ||x|| * C^-0.5
        s_inv = 1.f / fmaxf(nrm, 1e-6f);
    }
    __syncthreads();
    float inv = s_inv;
    const float4 nw = ((const float4*)norm_w)[threadIdx.x];
    const float4 sc = ((const float4*)(g_scale + (size_t)b*EMBED))[threadIdx.x];
    const float4 sh = ((const float4*)(g_shift + (size_t)b*EMBED))[threadIdx.x];
    float4 o;
    o.x = v.x * inv * nw.x * sc.x + sh.x;
    o.y = v.y * inv * nw.y * sc.y + sh.y;
    o.z = v.z * inv * nw.z * sc.z + sh.z;
    o.w = v.w * inv * nw.w * sc.w + sh.w;
    ((float4*)(g_xa + (size_t)row * EMBED))[threadIdx.x] = o;
}

// ---------------- tf32 tensor-core GEMM ------------------------------------
// C[m][n] = sum_k A[m][k]*W[n][k] (+bias)(+res), via mma.m16n8k8.tf32
// CTA tile 128x128, BK=32, 256 thr = 8 warps (2 M x 4 N), warp tile 64x32.
// ASEL: 0=g_xa 1=g_attn 2=g_hg ; CSEL: 0=g_qkv 1=g_x1 2=g_h 3=param
template<int ASEL, int CSEL, bool BIAS, bool RESX, bool RESG>
__global__ __launch_bounds__(256)
void tgemm_kernel(const float* __restrict__ W, const float* __restrict__ bias,
                  const float* __restrict__ resx, float* __restrict__ Cext,
                  int M, int Nn, int K) {
    const float* A = (ASEL == 0) ? g_xa : (ASEL == 1) ? g_attn : g_hg;
    float*       C = (CSEL == 0) ? g_qkv : (CSEL == 1) ? g_x1 : (CSEL == 2) ? g_h : Cext;

    __shared__ __align__(16) unsigned As[128][36];   // [m][k] tf32, pad 4
    __shared__ __align__(16) unsigned Bs[128][36];   // [n][k] tf32, pad 4

    int tid  = threadIdx.x;
    int lane = tid & 31;
    int wid  = tid >> 5;
    int wm   = wid & 1;          // 0..1  (M)
    int wn   = wid >> 1;         // 0..3  (N)
    int g    = lane >> 2;        // groupID 0..7
    int t    = lane & 3;         // thread-in-group 0..3

    int bm = blockIdx.y * 128, bn = blockIdx.x * 128;

    float acc[4][4][4];          // [mt][nt][c0..c3]
    #pragma unroll
    for (int i = 0; i < 4; i++)
        #pragma unroll
        for (int j = 0; j < 4; j++)
            #pragma unroll
            for (int r = 0; r < 4; r++) acc[i][j][r] = 0.f;

    for (int k0 = 0; k0 < K; k0 += 32) {
        // load + convert A,B tiles: 128 rows x 32 cols each (1024 float4 each)
        #pragma unroll
        for (int it = 0; it < 4; it++) {
            int idx = it * 256 + tid;        // 0..1023
            int r   = idx >> 3;
            int q   = (idx & 7) * 4;
            float4 av = *(const float4*)(A + (size_t)(bm + r) * K + k0 + q);
            float4 wv = *(const float4*)(W + (size_t)(bn + r) * K + k0 + q);
            uint4 at = make_uint4(f2tf32(av.x), f2tf32(av.y), f2tf32(av.z), f2tf32(av.w));
            uint4 wt = make_uint4(f2tf32(wv.x), f2tf32(wv.y), f2tf32(wv.z), f2tf32(wv.w));
            *(uint4*)&As[r][q] = at;
            *(uint4*)&Bs[r][q] = wt;
        }
        __syncthreads();

        #pragma unroll
        for (int ks = 0; ks < 4; ks++) {
            int kk = ks * 8;
            unsigned a[4][4], bfr[4][2];
            #pragma unroll
            for (int mt = 0; mt < 4; mt++) {
                int r0 = wm*64 + mt*16 + g;
                a[mt][0] = As[r0    ][kk + t];
                a[mt][1] = As[r0 + 8][kk + t];
                a[mt][2] = As[r0    ][kk + t + 4];
                a[mt][3] = As[r0 + 8][kk + t + 4];
            }
            #pragma unroll
            for (int nt = 0; nt < 4; nt++) {
                int n0 = wn*32 + nt*8 + g;
                bfr[nt][0] = Bs[n0][kk + t];
                bfr[nt][1] = Bs[n0][kk + t + 4];
            }
            #pragma unroll
            for (int mt = 0; mt < 4; mt++)
                #pragma unroll
                for (int nt = 0; nt < 4; nt++) {
                    asm volatile(
                        "mma.sync.aligned.m16n8k8.row.col.f32.tf32.tf32.f32 "
                        "{%0,%1,%2,%3}, {%4,%5,%6,%7}, {%8,%9}, {%0,%1,%2,%3};"
                        : "+f"(acc[mt][nt][0]), "+f"(acc[mt][nt][1]),
                          "+f"(acc[mt][nt][2]), "+f"(acc[mt][nt][3])
                        : "r"(a[mt][0]), "r"(a[mt][1]), "r"(a[mt][2]), "r"(a[mt][3]),
                          "r"(bfr[nt][0]), "r"(bfr[nt][1]));
                }
        }
        __syncthreads();
    }

    // epilogue: c0,c1 -> (row g, cols 2t,2t+1); c2,c3 -> (row g+8)
    #pragma unroll
    for (int mt = 0; mt < 4; mt++) {
        int r0 = bm + wm*64 + mt*16 + g;
        int r1 = r0 + 8;
        #pragma unroll
        for (int nt = 0; nt < 4; nt++) {
            int cc = bn + wn*32 + nt*8 + t*2;
            float v0 = acc[mt][nt][0], v1 = acc[mt][nt][1];
            float v2 = acc[mt][nt][2], v3 = acc[mt][nt][3];
            if (BIAS) { float b0 = bias[cc], b1 = bias[cc+1]; v0 += b0; v1 += b1; v2 += b0; v3 += b1; }
            if (RESX) {
                const float2 p0 = *(const float2*)(resx + (size_t)r0 * Nn + cc);
                const float2 p1 = *(const float2*)(resx + (size_t)r1 * Nn + cc);
                v0 += p0.x; v1 += p0.y; v2 += p1.x; v3 += p1.y;
            }
            if (RESG) {
                const float2 p0 = *(const float2*)(g_x1 + (size_t)r0 * Nn + cc);
                const float2 p1 = *(const float2*)(g_x1 + (size_t)r1 * Nn + cc);
                v0 += p0.x; v1 += p0.y; v2 += p1.x; v3 += p1.y;
            }
            *(float2*)(C + (size_t)r0 * Nn + cc) = make_float2(v0, v1);
            *(float2*)(C + (size_t)r1 * Nn + cc) = make_float2(v2, v3);
        }
    }
}

// ---------------- flash attention (32 queries x 64-key tiles, D=64) -------
__global__ __launch_bounds__(256)
void attn_kernel(const int* __restrict__ mask) {
    __shared__ __align__(16) float qs[32*65];
    __shared__ __align__(16) float ks[64*65];   // reused for P tile
    __shared__ __align__(16) float vs[64*64];
    __shared__ int msk[64];

    int tid = threadIdx.x;
    int tx = tid & 15, ty = tid >> 4;
    int qt = blockIdx.x, h = blockIdx.y, b = blockIdx.z;
    int q0 = qt * 32;

    for (int i = tid; i < 512; i += 256) {
        int r = i >> 4, c4 = (i & 15) * 4;
        float4 v = *(const float4*)(g_qkv + (size_t)(b*SEQ + q0 + r) * 3072 + h*HDIM + c4);
        qs[r*65 + c4+0] = v.x; qs[r*65 + c4+1] = v.y;
        qs[r*65 + c4+2] = v.z; qs[r*65 + c4+3] = v.w;
    }

    float m[2], l[2], acc[2][4];
    #pragma unroll
    for (int i = 0; i < 2; i++) {
        m[i] = NEG_INF; l[i] = 0.f;
        #pragma unroll
        for (int j = 0; j < 4; j++) acc[i][j] = 0.f;
    }

    for (int kt = 0; kt < SEQ/64; kt++) {
        __syncthreads();
        for (int i = tid; i < 1024; i += 256) {
            int r = i >> 4, c4 = (i & 15) * 4;
            const float* base = g_qkv + (size_t)(b*SEQ + kt*64 + r) * 3072 + h*HDIM;
            float4 kv = *(const float4*)(base + 1024 + c4);
            float4 vv = *(const float4*)(base + 2048 + c4);
            ks[r*65 + c4+0] = kv.x; ks[r*65 + c4+1] = kv.y;
            ks[r*65 + c4+2] = kv.z; ks[r*65 + c4+3] = kv.w;
            vs[r*64 + c4+0] = vv.x; vs[r*64 + c4+1] = vv.y;
            vs[r*64 + c4+2] = vv.z; vs[r*64 + c4+3] = vv.w;
        }
        if (tid < 64) msk[tid] = mask[b*SEQ + kt*64 + tid];
        __syncthreads();

        float s[2][4];
        #pragma unroll
        for (int i = 0; i < 2; i++)
            #pragma unroll
            for (int j = 0; j < 4; j++) s[i][j] = 0.f;
        #pragma unroll 8
        for (int d = 0; d < 64; d++) {
            float aq[2], bk[4];
            #pragma unroll
            for (int i = 0; i < 2; i++) aq[i] = qs[(ty*2+i)*65 + d];
            #pragma unroll
            for (int j = 0; j < 4; j++) bk[j] = ks[(tx*4+j)*65 + d];
            #pragma unroll
            for (int i = 0; i < 2; i++)
                #pragma unroll
                for (int j = 0; j < 4; j++) s[i][j] = fmaf(aq[i], bk[j], s[i][j]);
        }

        #pragma unroll
        for (int i = 0; i < 2; i++) {
            float tmax = NEG_INF;
            #pragma unroll
            for (int j = 0; j < 4; j++) {
                s[i][j] = msk[tx*4+j] ? s[i][j] * 0.125f : NEG_INF;
                tmax = fmaxf(tmax, s[i][j]);
            }
            #pragma unroll
            for (int off = 8; off; off >>= 1)
                tmax = fmaxf(tmax, __shfl_xor_sync(0xffffffffu, tmax, off, 16));
            float mnew = fmaxf(m[i], tmax);
            float alpha, psum = 0.f;
            if (mnew <= NEG_INF) {
                alpha = 1.f;
                #pragma unroll
                for (int j = 0; j < 4; j++) s[i][j] = 0.f;
            } else {
                alpha = expf(m[i] - mnew);
                #pragma unroll
                for (int j = 0; j < 4; j++) {
                    float p = expf(s[i][j] - mnew);
                    s[i][j] = p; psum += p;
                }
            }
            #pragma unroll
            for (int off = 8; off; off >>= 1)
                psum += __shfl_xor_sync(0xffffffffu, psum, off, 16);
            l[i] = l[i] * alpha + psum;
            m[i] = mnew;
            #pragma unroll
            for (int d = 0; d < 4; d++) acc[i][d] *= alpha;
        }

        __syncthreads();
        #pragma unroll
        for (int i = 0; i < 2; i++)
            #pragma unroll
            for (int j = 0; j < 4; j++)
                ks[(ty*2+i)*65 + tx*4+j] = s[i][j];     // P tile (32x64)
        __syncthreads();

        #pragma unroll 8
        for (int j = 0; j < 64; j++) {
            float ap[2];
            #pragma unroll
            for (int i = 0; i < 2; i++) ap[i] = ks[(ty*2+i)*65 + j];
            float4 vv = *(const float4*)&vs[j*64 + tx*4];
            #pragma unroll
            for (int i = 0; i < 2; i++) {
                acc[i][0] = fmaf(ap[i], vv.x, acc[i][0]);
                acc[i][1] = fmaf(ap[i], vv.y, acc[i][1]);
                acc[i][2] = fmaf(ap[i], vv.z, acc[i][2]);
                acc[i][3] = fmaf(ap[i], vv.w, acc[i][3]);
            }
        }
    }

    #pragma unroll
    for (int i = 0; i < 2; i++) {
        float invl = (l[i] > 0.f) ? (1.f / l[i]) : 0.f;
        int t = q0 + ty*2 + i;
        float4 o = make_float4(acc[i][0]*invl, acc[i][1]*invl, acc[i][2]*invl, acc[i][3]*invl);
        *(float4*)(g_attn + (size_t)(b*SEQ + t) * EMBED + h*HDIM + tx*4) = o;
    }
}

// ---------------- swiglu: g_hg = silu(g_h[:, :MLPD]) * g_h[:, MLPD:] ------
__global__ void swiglu_kernel() {
    int idx = blockIdx.x * blockDim.x + threadIdx.x;
    int row = idx >> 10;
    int c4  = (idx & 1023) * 4;
    const float* base = g_h + (size_t)row * (2*MLPD);
    float4 a = *(const float4*)(base + c4);
    float4 g = *(const float4*)(base + MLPD + c4);
    float4 o;
    o.x = a.x / (1.f + expf(-a.x)) * g.x;
    o.y = a.y / (1.f + expf(-a.y)) * g.y;
    o.z = a.z / (1.f + expf(-a.z)) * g.z;
    o.w = a.w / (1.f + expf(-a.w)) * g.w;
    *(float4*)(g_hg + (size_t)row * MLPD + c4) = o;
}

// ------------------------------ launch ------------------------------------
static const int SIG_DECL[15] = {4194304,2048,4096,1024,1048576,1024,1048576,1024,
                                3145728,1048576,1024,8388608,8192,4194304,1024};
static const int SIG_ALPHA[15] = {4096,2048,8192,1024,8388608,4194304,1024,1024,
                                  1048576,3145728,1024,1048576,1024,1048576,4194304};
static const int MAP_ALPHA[15] = {14,1,0,6,11,10,13,12,9,8,7,4,2,5,3};

extern "C" void kernel_launch(void* const* d_in, const int* in_sizes, int n_in,
                              void* d_out, int out_size) {
    const void* in[15];
    bool decl_ok = (n_in >= 15), alpha_ok = (n_in >= 15);
    for (int i = 0; i < 15 && i < n_in; i++) {
        if (in_sizes[i] != SIG_DECL[i])  decl_ok = false;
        if (in_sizes[i] != SIG_ALPHA[i]) alpha_ok = false;
    }
    if (!decl_ok && alpha_ok) {
        for (int r = 0; r < 15; r++) in[r] = d_in[MAP_ALPHA[r]];
    } else {
        for (int r = 0; r < 15; r++) in[r] = d_in[r];
    }

    const float* x      = (const float*)in[0];
    const float* c      = (const float*)in[1];
    const int*   amask  = (const int*)  in[2];
    const float* norm_w = (const float*)in[3];
    const float* scale_w= (const float*)in[4];
    const float* scale_b= (const float*)in[5];
    const float* shift_w= (const float*)in[6];
    const float* shift_b= (const float*)in[7];
    const float* qkv_w  = (const float*)in[8];
    const float* proj_w = (const float*)in[9];
    const float* proj_b = (const float*)in[10];
    const float* mlp_w1 = (const float*)in[11];
    const float* mlp_b1 = (const float*)in[12];
    const float* mlp_w2 = (const float*)in[13];
    const float* mlp_b2 = (const float*)in[14];
    float* out = (float*)d_out;

    // 1) adaLN modulation vectors (shared by both adaLN calls)
    modvec_kernel<<<512, 256>>>(c, shift_w, shift_b, scale_w, scale_b);
    // 2) g_xa = adaLN(x)
    adaln_kernel<0><<<ROWS, 256>>>(x, norm_w);
    // 3) g_qkv = g_xa @ qkv_w.T
    tgemm_kernel<0,0,false,false,false><<<dim3(3*EMBED/128, ROWS/128), 256>>>(
        qkv_w, nullptr, nullptr, nullptr, ROWS, 3*EMBED, EMBED);
    // 4) g_attn = flashattn(g_qkv)
    attn_kernel<<<dim3(SEQ/32, HEADS, BATCH), 256>>>(amask);
    // 5) g_x1 = x + g_attn @ proj_w.T + proj_b
    tgemm_kernel<1,1,true,true,false><<<dim3(EMBED/128, ROWS/128), 256>>>(
        proj_w, proj_b, x, nullptr, ROWS, EMBED, EMBED);
    // 6) g_xa = adaLN(g_x1)
    adaln_kernel<1><<<ROWS, 256>>>(nullptr, norm_w);
    // 7) g_h = g_xa @ mlp_w1.T + mlp_b1
    tgemm_kernel<0,2,true,false,false><<<dim3(2*MLPD/128, ROWS/128), 256>>>(
        mlp_w1, mlp_b1, nullptr, nullptr, ROWS, 2*MLPD, EMBED);
    // 8) g_hg = swiglu(g_h)
    swiglu_kernel<<<ROWS*(MLPD/4)/256, 256>>>();
    // 9) out = g_x1 + g_hg @ mlp_w2.T + mlp_b2
    tgemm_kernel<2,3,true,false,true><<<dim3(EMBED/128, ROWS/128), 256>>>(
        mlp_w2, mlp_b2, nullptr, out, ROWS, EMBED, MLPD);
}

// round 8
// speedup vs baseline: 5.2919x; 1.8391x over previous
#include <cuda_runtime.h>
#include <cuda_fp16.h>
#include <math.h>

#define BATCH 2
#define SEQ   2048
#define EMBED 1024
#define HEADS 16
#define HDIM  64
#define MLPD  4096
#define ROWS  (BATCH*SEQ)          // 4096
#define NEG_INF (-1e30f)

// ---------------- scratch (device globals; zero-init BSS; 16B-aligned) ----
__device__ __align__(16) float g_shift[BATCH*EMBED];
__device__ __align__(16) float g_scale[BATCH*EMBED];
__device__ __align__(16) float g_xa  [ROWS*EMBED];
__device__ __align__(16) float g_qkv [ROWS*3*EMBED];
__device__ __align__(16) float g_attn[ROWS*EMBED];
__device__ __align__(16) float g_x1  [ROWS*EMBED];
__device__ __align__(16) float g_h   [ROWS*2*MLPD];
__device__ __align__(16) float g_hg  [ROWS*MLPD];

__device__ __forceinline__ unsigned f2tf32(float f) {
    unsigned r;
    asm("cvt.rna.tf32.f32 %0, %1;" : "=r"(r) : "f"(f));
    return r;
}
__device__ __forceinline__ unsigned packh2(float lo, float hi) {
    __half2 h = __floats2half2_rn(lo, hi);
    return *reinterpret_cast<unsigned*>(&h);
}

// ---------------- adaLN modulation vectors -> g_shift / g_scale -----------
__global__ void modvec_kernel(const float* __restrict__ c,
                              const float* __restrict__ shift_w, const float* __restrict__ shift_b,
                              const float* __restrict__ scale_w, const float* __restrict__ scale_b) {
    int gw   = (blockIdx.x * blockDim.x + threadIdx.x) >> 5;
    int lane = threadIdx.x & 31;
    int which = gw >> 11;
    int b     = (gw >> 10) & 1;
    int j     = gw & 1023;
    const float* w  = (which ? scale_w : shift_w) + (size_t)j * EMBED;
    const float* cb = c + b * EMBED;
    float acc = 0.f;
    for (int k = lane; k < EMBED; k += 32) {
        float cv = cb[k];
        float s  = cv / (1.f + expf(-cv));
        acc += s * w[k];
    }
    #pragma unroll
    for (int off = 16; off; off >>= 1) acc += __shfl_xor_sync(0xffffffffu, acc, off);
    if (lane == 0) {
        if (which == 0) g_shift[b*EMBED + j] = acc + shift_b[j];
        else {
            float v = acc + scale_b[j] + 1.0f;
            g_scale[b*EMBED + j] = fminf(fmaxf(v, 0.1f), 10.0f);
        }
    }
}

// ---------------- RMS-like norm + modulate; SRC=0: param x, SRC=1: g_x1 ---
template<int SRC>
__global__ void adaln_kernel(const float* __restrict__ xext, const float* __restrict__ norm_w) {
    int row = blockIdx.x;
    int b   = row >> 11;
    const float* xp = (SRC == 0) ? xext : g_x1;
    const float4* xr = (const float4*)(xp + (size_t)row * EMBED);
    float4 v = xr[threadIdx.x];
    float ss = v.x*v.x + v.y*v.y + v.z*v.z + v.w*v.w;
    __shared__ float red[8];
    #pragma unroll
    for (int off = 16; off; off >>= 1) ss += __shfl_xor_sync(0xffffffffu, ss, off);
    if ((threadIdx.x & 31) == 0) red[threadIdx.x >> 5] = ss;
    __syncthreads();
    __shared__ float s_inv;
    if (threadIdx.x == 0) {
        float t = 0.f;
        #pragma unroll
        for (int i = 0; i < 8; i++) t += red[i];
        float nrm = sqrtf(t) * (1.f / 32.f);
        s_inv = 1.f / fmaxf(nrm, 1e-6f);
    }
    __syncthreads();
    float inv = s_inv;
    const float4 nw = ((const float4*)norm_w)[threadIdx.x];
    const float4 sc = ((const float4*)(g_scale + (size_t)b*EMBED))[threadIdx.x];
    const float4 sh = ((const float4*)(g_shift + (size_t)b*EMBED))[threadIdx.x];
    float4 o;
    o.x = v.x * inv * nw.x * sc.x + sh.x;
    o.y = v.y * inv * nw.y * sc.y + sh.y;
    o.z = v.z * inv * nw.z * sc.z + sh.z;
    o.w = v.w * inv * nw.w * sc.w + sh.w;
    ((float4*)(g_xa + (size_t)row * EMBED))[threadIdx.x] = o;
}

// ---------------- tf32 tensor-core GEMM (unchanged from R5) ---------------
template<int ASEL, int CSEL, bool BIAS, bool RESX, bool RESG>
__global__ __launch_bounds__(256)
void tgemm_kernel(const float* __restrict__ W, const float* __restrict__ bias,
                  const float* __restrict__ resx, float* __restrict__ Cext,
                  int M, int Nn, int K) {
    const float* A = (ASEL == 0) ? g_xa : (ASEL == 1) ? g_attn : g_hg;
    float*       C = (CSEL == 0) ? g_qkv : (CSEL == 1) ? g_x1 : (CSEL == 2) ? g_h : Cext;

    __shared__ __align__(16) unsigned As[128][36];
    __shared__ __align__(16) unsigned Bs[128][36];

    int tid  = threadIdx.x;
    int lane = tid & 31;
    int wid  = tid >> 5;
    int wm   = wid & 1;
    int wn   = wid >> 1;
    int g    = lane >> 2;
    int t    = lane & 3;

    int bm = blockIdx.y * 128, bn = blockIdx.x * 128;

    float acc[4][4][4];
    #pragma unroll
    for (int i = 0; i < 4; i++)
        #pragma unroll
        for (int j = 0; j < 4; j++)
            #pragma unroll
            for (int r = 0; r < 4; r++) acc[i][j][r] = 0.f;

    for (int k0 = 0; k0 < K; k0 += 32) {
        #pragma unroll
        for (int it = 0; it < 4; it++) {
            int idx = it * 256 + tid;
            int r   = idx >> 3;
            int q   = (idx & 7) * 4;
            float4 av = *(const float4*)(A + (size_t)(bm + r) * K + k0 + q);
            float4 wv = *(const float4*)(W + (size_t)(bn + r) * K + k0 + q);
            uint4 at = make_uint4(f2tf32(av.x), f2tf32(av.y), f2tf32(av.z), f2tf32(av.w));
            uint4 wt = make_uint4(f2tf32(wv.x), f2tf32(wv.y), f2tf32(wv.z), f2tf32(wv.w));
            *(uint4*)&As[r][q] = at;
            *(uint4*)&Bs[r][q] = wt;
        }
        __syncthreads();

        #pragma unroll
        for (int ks = 0; ks < 4; ks++) {
            int kk = ks * 8;
            unsigned a[4][4], bfr[4][2];
            #pragma unroll
            for (int mt = 0; mt < 4; mt++) {
                int r0 = wm*64 + mt*16 + g;
                a[mt][0] = As[r0    ][kk + t];
                a[mt][1] = As[r0 + 8][kk + t];
                a[mt][2] = As[r0    ][kk + t + 4];
                a[mt][3] = As[r0 + 8][kk + t + 4];
            }
            #pragma unroll
            for (int nt = 0; nt < 4; nt++) {
                int n0 = wn*32 + nt*8 + g;
                bfr[nt][0] = Bs[n0][kk + t];
                bfr[nt][1] = Bs[n0][kk + t + 4];
            }
            #pragma unroll
            for (int mt = 0; mt < 4; mt++)
                #pragma unroll
                for (int nt = 0; nt < 4; nt++) {
                    asm volatile(
                        "mma.sync.aligned.m16n8k8.row.col.f32.tf32.tf32.f32 "
                        "{%0,%1,%2,%3}, {%4,%5,%6,%7}, {%8,%9}, {%0,%1,%2,%3};"
                        : "+f"(acc[mt][nt][0]), "+f"(acc[mt][nt][1]),
                          "+f"(acc[mt][nt][2]), "+f"(acc[mt][nt][3])
                        : "r"(a[mt][0]), "r"(a[mt][1]), "r"(a[mt][2]), "r"(a[mt][3]),
                          "r"(bfr[nt][0]), "r"(bfr[nt][1]));
                }
        }
        __syncthreads();
    }

    #pragma unroll
    for (int mt = 0; mt < 4; mt++) {
        int r0 = bm + wm*64 + mt*16 + g;
        int r1 = r0 + 8;
        #pragma unroll
        for (int nt = 0; nt < 4; nt++) {
            int cc = bn + wn*32 + nt*8 + t*2;
            float v0 = acc[mt][nt][0], v1 = acc[mt][nt][1];
            float v2 = acc[mt][nt][2], v3 = acc[mt][nt][3];
            if (BIAS) { float b0 = bias[cc], b1 = bias[cc+1]; v0 += b0; v1 += b1; v2 += b0; v3 += b1; }
            if (RESX) {
                const float2 p0 = *(const float2*)(resx + (size_t)r0 * Nn + cc);
                const float2 p1 = *(const float2*)(resx + (size_t)r1 * Nn + cc);
                v0 += p0.x; v1 += p0.y; v2 += p1.x; v3 += p1.y;
            }
            if (RESG) {
                const float2 p0 = *(const float2*)(g_x1 + (size_t)r0 * Nn + cc);
                const float2 p1 = *(const float2*)(g_x1 + (size_t)r1 * Nn + cc);
                v0 += p0.x; v1 += p0.y; v2 += p1.x; v3 += p1.y;
            }
            *(float2*)(C + (size_t)r0 * Nn + cc) = make_float2(v0, v1);
            *(float2*)(C + (size_t)r1 * Nn + cc) = make_float2(v2, v3);
        }
    }
}

// ---------------- tensor-core flash attention ------------------------------
// 64 queries/block, 64-key tiles. 4 warps, each warp owns 16 query rows.
// QK^T: tf32 m16n8k8.  P@V: fp16 m16n8k16 (P pack needs no shuffles).
// grid: (SEQ/64, HEADS, BATCH), block 128.
__global__ __launch_bounds__(128)
void attn_kernel(const int* __restrict__ mask) {
    __shared__ __align__(16) unsigned qs[64][68];   // [q][d] tf32
    __shared__ __align__(16) unsigned ks[64][68];   // [j][d] tf32
    __shared__ __align__(16) __half   vs[64][72];   // [d][j] fp16 (transposed)
    __shared__ int msk[64];

    int tid  = threadIdx.x;
    int lane = tid & 31, w = tid >> 5;
    int g = lane >> 2, t = lane & 3;
    int q0 = blockIdx.x * 64, h = blockIdx.y, b = blockIdx.z;

    // load Q tile (64x64) -> tf32
    for (int i = tid; i < 1024; i += 128) {
        int r = i >> 4, c4 = (i & 15) * 4;
        float4 v = *(const float4*)(g_qkv + (size_t)(b*SEQ + q0 + r)*3072 + h*HDIM + c4);
        qs[r][c4+0] = f2tf32(v.x); qs[r][c4+1] = f2tf32(v.y);
        qs[r][c4+2] = f2tf32(v.z); qs[r][c4+3] = f2tf32(v.w);
    }

    float m0 = NEG_INF, m1 = NEG_INF, l0 = 0.f, l1 = 0.f;
    float o[8][4];
    #pragma unroll
    for (int dt = 0; dt < 8; dt++)
        #pragma unroll
        for (int r = 0; r < 4; r++) o[dt][r] = 0.f;

    for (int kt = 0; kt < SEQ/64; kt++) {
        __syncthreads();
        for (int i = tid; i < 1024; i += 128) {
            int r = i >> 4, c4 = (i & 15) * 4;
            const float* base = g_qkv + (size_t)(b*SEQ + kt*64 + r)*3072 + h*HDIM;
            float4 kv = *(const float4*)(base + 1024 + c4);
            float4 vv = *(const float4*)(base + 2048 + c4);
            ks[r][c4+0] = f2tf32(kv.x); ks[r][c4+1] = f2tf32(kv.y);
            ks[r][c4+2] = f2tf32(kv.z); ks[r][c4+3] = f2tf32(kv.w);
            vs[c4+0][r] = __float2half_rn(vv.x);
            vs[c4+1][r] = __float2half_rn(vv.y);
            vs[c4+2][r] = __float2half_rn(vv.z);
            vs[c4+3][r] = __float2half_rn(vv.w);
        }
        if (tid < 64) msk[tid] = mask[b*SEQ + kt*64 + tid];
        __syncthreads();

        // S = Q K^T (16x64 per warp)
        float s[8][4];
        #pragma unroll
        for (int nt = 0; nt < 8; nt++)
            #pragma unroll
            for (int r = 0; r < 4; r++) s[nt][r] = 0.f;

        #pragma unroll
        for (int kk = 0; kk < 8; kk++) {
            int k8 = kk * 8;
            unsigned a0 = qs[w*16 + g    ][k8 + t];
            unsigned a1 = qs[w*16 + g + 8][k8 + t];
            unsigned a2 = qs[w*16 + g    ][k8 + t + 4];
            unsigned a3 = qs[w*16 + g + 8][k8 + t + 4];
            #pragma unroll
            for (int nt = 0; nt < 8; nt++) {
                unsigned b0 = ks[nt*8 + g][k8 + t];
                unsigned b1 = ks[nt*8 + g][k8 + t + 4];
                asm volatile(
                    "mma.sync.aligned.m16n8k8.row.col.f32.tf32.tf32.f32 "
                    "{%0,%1,%2,%3}, {%4,%5,%6,%7}, {%8,%9}, {%0,%1,%2,%3};"
                    : "+f"(s[nt][0]), "+f"(s[nt][1]), "+f"(s[nt][2]), "+f"(s[nt][3])
                    : "r"(a0), "r"(a1), "r"(a2), "r"(a3), "r"(b0), "r"(b1));
            }
        }

        // mask + scale, find row maxes (rows g and g+8)
        float pm0 = NEG_INF, pm1 = NEG_INF;
        #pragma unroll
        for (int nt = 0; nt < 8; nt++) {
            int c0 = nt*8 + 2*t;
            bool k0 = msk[c0] != 0, k1 = msk[c0+1] != 0;
            s[nt][0] = k0 ? s[nt][0]*0.125f : NEG_INF;
            s[nt][1] = k1 ? s[nt][1]*0.125f : NEG_INF;
            s[nt][2] = k0 ? s[nt][2]*0.125f : NEG_INF;
            s[nt][3] = k1 ? s[nt][3]*0.125f : NEG_INF;
            pm0 = fmaxf(pm0, fmaxf(s[nt][0], s[nt][1]));
            pm1 = fmaxf(pm1, fmaxf(s[nt][2], s[nt][3]));
        }
        pm0 = fmaxf(pm0, __shfl_xor_sync(0xffffffffu, pm0, 1));
        pm0 = fmaxf(pm0, __shfl_xor_sync(0xffffffffu, pm0, 2));
        pm1 = fmaxf(pm1, __shfl_xor_sync(0xffffffffu, pm1, 1));
        pm1 = fmaxf(pm1, __shfl_xor_sync(0xffffffffu, pm1, 2));

        float mn0 = fmaxf(m0, pm0), mn1 = fmaxf(m1, pm1);
        float al0, al1, ps0 = 0.f, ps1 = 0.f;
        if (mn0 <= NEG_INF) {
            al0 = 1.f;
            #pragma unroll
            for (int nt = 0; nt < 8; nt++) { s[nt][0] = 0.f; s[nt][1] = 0.f; }
        } else {
            al0 = expf(m0 - mn0);
            #pragma unroll
            for (int nt = 0; nt < 8; nt++) {
                float p0 = expf(s[nt][0] - mn0), p1 = expf(s[nt][1] - mn0);
                s[nt][0] = p0; s[nt][1] = p1; ps0 += p0 + p1;
            }
        }
        if (mn1 <= NEG_INF) {
            al1 = 1.f;
            #pragma unroll
            for (int nt = 0; nt < 8; nt++) { s[nt][2] = 0.f; s[nt][3] = 0.f; }
        } else {
            al1 = expf(m1 - mn1);
            #pragma unroll
            for (int nt = 0; nt < 8; nt++) {
                float p2 = expf(s[nt][2] - mn1), p3 = expf(s[nt][3] - mn1);
                s[nt][2] = p2; s[nt][3] = p3; ps1 += p2 + p3;
            }
        }
        ps0 += __shfl_xor_sync(0xffffffffu, ps0, 1);
        ps0 += __shfl_xor_sync(0xffffffffu, ps0, 2);
        ps1 += __shfl_xor_sync(0xffffffffu, ps1, 1);
        ps1 += __shfl_xor_sync(0xffffffffu, ps1, 2);
        l0 = l0 * al0 + ps0; m0 = mn0;
        l1 = l1 * al1 + ps1; m1 = mn1;
        #pragma unroll
        for (int dt = 0; dt < 8; dt++) {
            o[dt][0] *= al0; o[dt][1] *= al0;
            o[dt][2] *= al1; o[dt][3] *= al1;
        }

        // O += P @ V  (fp16 m16n8k16; P fragments come straight from S regs)
        #pragma unroll
        for (int ki = 0; ki < 4; ki++) {
            unsigned a0 = packh2(s[2*ki  ][0], s[2*ki  ][1]);
            unsigned a1 = packh2(s[2*ki  ][2], s[2*ki  ][3]);
            unsigned a2 = packh2(s[2*ki+1][0], s[2*ki+1][1]);
            unsigned a3 = packh2(s[2*ki+1][2], s[2*ki+1][3]);
            #pragma unroll
            for (int dt = 0; dt < 8; dt++) {
                unsigned b0 = *(const unsigned*)&vs[dt*8 + g][ki*16 + 2*t];
                unsigned b1 = *(const unsigned*)&vs[dt*8 + g][ki*16 + 8 + 2*t];
                asm volatile(
                    "mma.sync.aligned.m16n8k16.row.col.f32.f16.f16.f32 "
                    "{%0,%1,%2,%3}, {%4,%5,%6,%7}, {%8,%9}, {%0,%1,%2,%3};"
                    : "+f"(o[dt][0]), "+f"(o[dt][1]), "+f"(o[dt][2]), "+f"(o[dt][3])
                    : "r"(a0), "r"(a1), "r"(a2), "r"(a3), "r"(b0), "r"(b1));
            }
        }
    }

    float il0 = (l0 > 0.f) ? 1.f/l0 : 0.f;
    float il1 = (l1 > 0.f) ? 1.f/l1 : 0.f;
    size_t r0 = (size_t)(b*SEQ + q0 + w*16 + g) * EMBED + h*HDIM;
    size_t r1 = r0 + (size_t)8 * EMBED;
    #pragma unroll
    for (int dt = 0; dt < 8; dt++) {
        int cc = dt*8 + 2*t;
        *(float2*)(g_attn + r0 + cc) = make_float2(o[dt][0]*il0, o[dt][1]*il0);
        *(float2*)(g_attn + r1 + cc) = make_float2(o[dt][2]*il1, o[dt][3]*il1);
    }
}

// ---------------- swiglu: g_hg = silu(g_h[:, :MLPD]) * g_h[:, MLPD:] ------
__global__ void swiglu_kernel() {
    int idx = blockIdx.x * blockDim.x + threadIdx.x;
    int row = idx >> 10;
    int c4  = (idx & 1023) * 4;
    const float* base = g_h + (size_t)row * (2*MLPD);
    float4 a = *(const float4*)(base + c4);
    float4 g = *(const float4*)(base + MLPD + c4);
    float4 o;
    o.x = a.x / (1.f + expf(-a.x)) * g.x;
    o.y = a.y / (1.f + expf(-a.y)) * g.y;
    o.z = a.z / (1.f + expf(-a.z)) * g.z;
    o.w = a.w / (1.f + expf(-a.w)) * g.w;
    *(float4*)(g_hg + (size_t)row * MLPD + c4) = o;
}

// ------------------------------ launch ------------------------------------
static const int SIG_DECL[15] = {4194304,2048,4096,1024,1048576,1024,1048576,1024,
                                3145728,1048576,1024,8388608,8192,4194304,1024};
static const int SIG_ALPHA[15] = {4096,2048,8192,1024,8388608,4194304,1024,1024,
                                  1048576,3145728,1024,1048576,1024,1048576,4194304};
static const int MAP_ALPHA[15] = {14,1,0,6,11,10,13,12,9,8,7,4,2,5,3};

extern "C" void kernel_launch(void* const* d_in, const int* in_sizes, int n_in,
                              void* d_out, int out_size) {
    const void* in[15];
    bool decl_ok = (n_in >= 15), alpha_ok = (n_in >= 15);
    for (int i = 0; i < 15 && i < n_in; i++) {
        if (in_sizes[i] != SIG_DECL[i])  decl_ok = false;
        if (in_sizes[i] != SIG_ALPHA[i]) alpha_ok = false;
    }
    if (!decl_ok && alpha_ok) {
        for (int r = 0; r < 15; r++) in[r] = d_in[MAP_ALPHA[r]];
    } else {
        for (int r = 0; r < 15; r++) in[r] = d_in[r];
    }

    const float* x      = (const float*)in[0];
    const float* c      = (const float*)in[1];
    const int*   amask  = (const int*)  in[2];
    const float* norm_w = (const float*)in[3];
    const float* scale_w= (const float*)in[4];
    const float* scale_b= (const float*)in[5];
    const float* shift_w= (const float*)in[6];
    const float* shift_b= (const float*)in[7];
    const float* qkv_w  = (const float*)in[8];
    const float* proj_w = (const float*)in[9];
    const float* proj_b = (const float*)in[10];
    const float* mlp_w1 = (const float*)in[11];
    const float* mlp_b1 = (const float*)in[12];
    const float* mlp_w2 = (const float*)in[13];
    const float* mlp_b2 = (const float*)in[14];
    float* out = (float*)d_out;

    modvec_kernel<<<512, 256>>>(c, shift_w, shift_b, scale_w, scale_b);
    adaln_kernel<0><<<ROWS, 256>>>(x, norm_w);
    tgemm_kernel<0,0,false,false,false><<<dim3(3*EMBED/128, ROWS/128), 256>>>(
        qkv_w, nullptr, nullptr, nullptr, ROWS, 3*EMBED, EMBED);
    attn_kernel<<<dim3(SEQ/64, HEADS, BATCH), 128>>>(amask);
    tgemm_kernel<1,1,true,true,false><<<dim3(EMBED/128, ROWS/128), 256>>>(
        proj_w, proj_b, x, nullptr, ROWS, EMBED, EMBED);
    adaln_kernel<1><<<ROWS, 256>>>(nullptr, norm_w);
    tgemm_kernel<0,2,true,false,false><<<dim3(2*MLPD/128, ROWS/128), 256>>>(
        mlp_w1, mlp_b1, nullptr, nullptr, ROWS, 2*MLPD, EMBED);
    swiglu_kernel<<<ROWS*(MLPD/4)/256, 256>>>();
    tgemm_kernel<2,3,true,false,true><<<dim3(EMBED/128, ROWS/128), 256>>>(
        mlp_w2, mlp_b2, nullptr, out, ROWS, EMBED, MLPD);
}

// round 10
// speedup vs baseline: 5.4400x; 1.0280x over previous
#include <cuda_runtime.h>
#include <cuda_fp16.h>
#include <math.h>

#define BATCH 2
#define SEQ   2048
#define EMBED 1024
#define HEADS 16
#define HDIM  64
#define MLPD  4096
#define ROWS  (BATCH*SEQ)          // 4096
#define NEG_INF (-1e30f)

// ---------------- scratch (device globals; zero-init BSS; 16B-aligned) ----
__device__ __align__(16) float g_shift[BATCH*EMBED];
__device__ __align__(16) float g_scale[BATCH*EMBED];
__device__ __align__(16) float g_xa  [ROWS*EMBED];
__device__ __align__(16) float g_qkv [ROWS*3*EMBED];
__device__ __align__(16) float g_attn[ROWS*EMBED];
__device__ __align__(16) float g_x1  [ROWS*EMBED];
__device__ __align__(16) float g_h   [ROWS*2*MLPD];
__device__ __align__(16) float g_hg  [ROWS*MLPD];

__device__ __forceinline__ unsigned f2tf32(float f) {
    unsigned r;
    asm("cvt.rna.tf32.f32 %0, %1;" : "=r"(r) : "f"(f));
    return r;
}
__device__ __forceinline__ unsigned packh2(float lo, float hi) {
    __half2 h = __floats2half2_rn(lo, hi);
    return *reinterpret_cast<unsigned*>(&h);
}
__device__ __forceinline__ void cpasync16(unsigned dst, const void* src) {
    asm volatile("cp.async.cg.shared.global [%0], [%1], 16;" :: "r"(dst), "l"(src));
}

// ---------------- adaLN modulation vectors -> g_shift / g_scale -----------
__global__ void modvec_kernel(const float* __restrict__ c,
                              const float* __restrict__ shift_w, const float* __restrict__ shift_b,
                              const float* __restrict__ scale_w, const float* __restrict__ scale_b) {
    int gw   = (blockIdx.x * blockDim.x + threadIdx.x) >> 5;
    int lane = threadIdx.x & 31;
    int which = gw >> 11;
    int b     = (gw >> 10) & 1;
    int j     = gw & 1023;
    const float* w  = (which ? scale_w : shift_w) + (size_t)j * EMBED;
    const float* cb = c + b * EMBED;
    float acc = 0.f;
    for (int k = lane; k < EMBED; k += 32) {
        float cv = cb[k];
        float s  = cv / (1.f + expf(-cv));
        acc += s * w[k];
    }
    #pragma unroll
    for (int off = 16; off; off >>= 1) acc += __shfl_xor_sync(0xffffffffu, acc, off);
    if (lane == 0) {
        if (which == 0) g_shift[b*EMBED + j] = acc + shift_b[j];
        else {
            float v = acc + scale_b[j] + 1.0f;
            g_scale[b*EMBED + j] = fminf(fmaxf(v, 0.1f), 10.0f);
        }
    }
}

// ---------------- RMS-like norm + modulate; SRC=0: param x, SRC=1: g_x1 ---
template<int SRC>
__global__ void adaln_kernel(const float* __restrict__ xext, const float* __restrict__ norm_w) {
    int row = blockIdx.x;
    int b   = row >> 11;
    const float* xp = (SRC == 0) ? xext : g_x1;
    const float4* xr = (const float4*)(xp + (size_t)row * EMBED);
    float4 v = xr[threadIdx.x];
    float ss = v.x*v.x + v.y*v.y + v.z*v.z + v.w*v.w;
    __shared__ float red[8];
    #pragma unroll
    for (int off = 16; off; off >>= 1) ss += __shfl_xor_sync(0xffffffffu, ss, off);
    if ((threadIdx.x & 31) == 0) red[threadIdx.x >> 5] = ss;
    __syncthreads();
    __shared__ float s_inv;
    if (threadIdx.x == 0) {
        float t = 0.f;
        #pragma unroll
        for (int i = 0; i < 8; i++) t += red[i];
        float nrm = sqrtf(t) * (1.f / 32.f);
        s_inv = 1.f / fmaxf(nrm, 1e-6f);
    }
    __syncthreads();
    float inv = s_inv;
    const float4 nw = ((const float4*)norm_w)[threadIdx.x];
    const float4 sc = ((const float4*)(g_scale + (size_t)b*EMBED))[threadIdx.x];
    const float4 sh = ((const float4*)(g_shift + (size_t)b*EMBED))[threadIdx.x];
    float4 o;
    o.x = v.x * inv * nw.x * sc.x + sh.x;
    o.y = v.y * inv * nw.y * sc.y + sh.y;
    o.z = v.z * inv * nw.z * sc.z + sh.z;
    o.w = v.w * inv * nw.w * sc.w + sh.w;
    ((float4*)(g_xa + (size_t)row * EMBED))[threadIdx.x] = o;
}

// ---------------- tf32 tensor-core GEMM, 2-stage cp.async pipeline --------
// C[m][n] = sum_k A[m][k]*W[n][k] (+bias)(+res)
// CTA 128x128, BK=32, 256 thr (2Mx4N warps), dyn smem 72KB (fp32 tiles,
// tf32 conversion at fragment-load time).
#define TGSM (128*36)     // one stage of one matrix, in floats
template<int ASEL, int CSEL, bool BIAS, bool RESX, bool RESG>
__global__ __launch_bounds__(256)
void tgemm_kernel(const float* __restrict__ W, const float* __restrict__ bias,
                  const float* __restrict__ resx, float* __restrict__ Cext,
                  int M, int Nn, int K) {
    const float* A = (ASEL == 0) ? g_xa : (ASEL == 1) ? g_attn : g_hg;
    float*       C = (CSEL == 0) ? g_qkv : (CSEL == 1) ? g_x1 : (CSEL == 2) ? g_h : Cext;

    extern __shared__ __align__(16) float smem[];
    float* sA = smem;                 // [2][128][36]
    float* sB = smem + 2*TGSM;        // [2][128][36]

    int tid  = threadIdx.x;
    int lane = tid & 31;
    int wid  = tid >> 5;
    int wm   = wid & 1;
    int wn   = wid >> 1;
    int g    = lane >> 2;
    int t    = lane & 3;

    int bm = blockIdx.y * 128, bn = blockIdx.x * 128;

    // per-thread copy coords: 8 x float4 per stage (4 for A, 4 for B)
    int cr[4], cq[4];
    #pragma unroll
    for (int it = 0; it < 4; it++) {
        int idx = it * 256 + tid;
        cr[it] = idx >> 3;
        cq[it] = (idx & 7) * 4;
    }

    float acc[4][4][4];
    #pragma unroll
    for (int i = 0; i < 4; i++)
        #pragma unroll
        for (int j = 0; j < 4; j++)
            #pragma unroll
            for (int r = 0; r < 4; r++) acc[i][j][r] = 0.f;

    const int NT = K >> 5;

    // prologue: stage 0
    {
        float* dA = sA; float* dB = sB;
        #pragma unroll
        for (int it = 0; it < 4; it++) {
            cpasync16((unsigned)__cvta_generic_to_shared(&dA[cr[it]*36 + cq[it]]),
                      A + (size_t)(bm + cr[it]) * K + cq[it]);
            cpasync16((unsigned)__cvta_generic_to_shared(&dB[cr[it]*36 + cq[it]]),
                      W + (size_t)(bn + cr[it]) * K + cq[it]);
        }
        asm volatile("cp.async.commit_group;");
    }

    for (int kt = 0; kt < NT; kt++) {
        asm volatile("cp.async.wait_group 0;" ::: "memory");
        __syncthreads();

        // issue next stage (overlaps with compute below)
        if (kt + 1 < NT) {
            int k0 = (kt + 1) << 5;
            float* dA = sA + ((kt + 1) & 1) * TGSM;
            float* dB = sB + ((kt + 1) & 1) * TGSM;
            #pragma unroll
            for (int it = 0; it < 4; it++) {
                cpasync16((unsigned)__cvta_generic_to_shared(&dA[cr[it]*36 + cq[it]]),
                          A + (size_t)(bm + cr[it]) * K + k0 + cq[it]);
                cpasync16((unsigned)__cvta_generic_to_shared(&dB[cr[it]*36 + cq[it]]),
                          W + (size_t)(bn + cr[it]) * K + k0 + cq[it]);
            }
        }
        asm volatile("cp.async.commit_group;");

        const float* cA = sA + (kt & 1) * TGSM;
        const float* cB = sB + (kt & 1) * TGSM;

        #pragma unroll
        for (int ks = 0; ks < 4; ks++) {
            int kk = ks * 8;
            unsigned a[4][4], bfr[4][2];
            #pragma unroll
            for (int mt = 0; mt < 4; mt++) {
                int r0 = wm*64 + mt*16 + g;
                a[mt][0] = f2tf32(cA[ r0     *36 + kk + t]);
                a[mt][1] = f2tf32(cA[(r0 + 8)*36 + kk + t]);
                a[mt][2] = f2tf32(cA[ r0     *36 + kk + t + 4]);
                a[mt][3] = f2tf32(cA[(r0 + 8)*36 + kk + t + 4]);
            }
            #pragma unroll
            for (int nt = 0; nt < 4; nt++) {
                int n0 = wn*32 + nt*8 + g;
                bfr[nt][0] = f2tf32(cB[n0*36 + kk + t]);
                bfr[nt][1] = f2tf32(cB[n0*36 + kk + t + 4]);
            }
            #pragma unroll
            for (int mt = 0; mt < 4; mt++)
                #pragma unroll
                for (int nt = 0; nt < 4; nt++) {
                    asm volatile(
                        "mma.sync.aligned.m16n8k8.row.col.f32.tf32.tf32.f32 "
                        "{%0,%1,%2,%3}, {%4,%5,%6,%7}, {%8,%9}, {%0,%1,%2,%3};"
                        : "+f"(acc[mt][nt][0]), "+f"(acc[mt][nt][1]),
                          "+f"(acc[mt][nt][2]), "+f"(acc[mt][nt][3])
                        : "r"(a[mt][0]), "r"(a[mt][1]), "r"(a[mt][2]), "r"(a[mt][3]),
                          "r"(bfr[nt][0]), "r"(bfr[nt][1]));
                }
        }
        // top-of-loop wait+sync protects buffer reuse next iteration
    }

    #pragma unroll
    for (int mt = 0; mt < 4; mt++) {
        int r0 = bm + wm*64 + mt*16 + g;
        int r1 = r0 + 8;
        #pragma unroll
        for (int nt = 0; nt < 4; nt++) {
            int cc = bn + wn*32 + nt*8 + t*2;
            float v0 = acc[mt][nt][0], v1 = acc[mt][nt][1];
            float v2 = acc[mt][nt][2], v3 = acc[mt][nt][3];
            if (BIAS) { float b0 = bias[cc], b1 = bias[cc+1]; v0 += b0; v1 += b1; v2 += b0; v3 += b1; }
            if (RESX) {
                const float2 p0 = *(const float2*)(resx + (size_t)r0 * Nn + cc);
                const float2 p1 = *(const float2*)(resx + (size_t)r1 * Nn + cc);
                v0 += p0.x; v1 += p0.y; v2 += p1.x; v3 += p1.y;
            }
            if (RESG) {
                const float2 p0 = *(const float2*)(g_x1 + (size_t)r0 * Nn + cc);
                const float2 p1 = *(const float2*)(g_x1 + (size_t)r1 * Nn + cc);
                v0 += p0.x; v1 += p0.y; v2 += p1.x; v3 += p1.y;
            }
            *(float2*)(C + (size_t)r0 * Nn + cc) = make_float2(v0, v1);
            *(float2*)(C + (size_t)r1 * Nn + cc) = make_float2(v2, v3);
        }
    }
}
#define TGEMM_SMEM (4*TGSM*(int)sizeof(float))   // 73728 B

// ---------------- tensor-core flash attention (unchanged from R7) ---------
__global__ __launch_bounds__(128)
void attn_kernel(const int* __restrict__ mask) {
    __shared__ __align__(16) unsigned qs[64][68];
    __shared__ __align__(16) unsigned ks[64][68];
    __shared__ __align__(16) __half   vs[64][72];
    __shared__ int msk[64];

    int tid  = threadIdx.x;
    int lane = tid & 31, w = tid >> 5;
    int g = lane >> 2, t = lane & 3;
    int q0 = blockIdx.x * 64, h = blockIdx.y, b = blockIdx.z;

    for (int i = tid; i < 1024; i += 128) {
        int r = i >> 4, c4 = (i & 15) * 4;
        float4 v = *(const float4*)(g_qkv + (size_t)(b*SEQ + q0 + r)*3072 + h*HDIM + c4);
        qs[r][c4+0] = f2tf32(v.x); qs[r][c4+1] = f2tf32(v.y);
        qs[r][c4+2] = f2tf32(v.z); qs[r][c4+3] = f2tf32(v.w);
    }

    float m0 = NEG_INF, m1 = NEG_INF, l0 = 0.f, l1 = 0.f;
    float o[8][4];
    #pragma unroll
    for (int dt = 0; dt < 8; dt++)
        #pragma unroll
        for (int r = 0; r < 4; r++) o[dt][r] = 0.f;

    for (int kt = 0; kt < SEQ/64; kt++) {
        __syncthreads();
        for (int i = tid; i < 1024; i += 128) {
            int r = i >> 4, c4 = (i & 15) * 4;
            const float* base = g_qkv + (size_t)(b*SEQ + kt*64 + r)*3072 + h*HDIM;
            float4 kv = *(const float4*)(base + 1024 + c4);
            float4 vv = *(const float4*)(base + 2048 + c4);
            ks[r][c4+0] = f2tf32(kv.x); ks[r][c4+1] = f2tf32(kv.y);
            ks[r][c4+2] = f2tf32(kv.z); ks[r][c4+3] = f2tf32(kv.w);
            vs[c4+0][r] = __float2half_rn(vv.x);
            vs[c4+1][r] = __float2half_rn(vv.y);
            vs[c4+2][r] = __float2half_rn(vv.z);
            vs[c4+3][r] = __float2half_rn(vv.w);
        }
        if (tid < 64) msk[tid] = mask[b*SEQ + kt*64 + tid];
        __syncthreads();

        float s[8][4];
        #pragma unroll
        for (int nt = 0; nt < 8; nt++)
            #pragma unroll
            for (int r = 0; r < 4; r++) s[nt][r] = 0.f;

        #pragma unroll
        for (int kk = 0; kk < 8; kk++) {
            int k8 = kk * 8;
            unsigned a0 = qs[w*16 + g    ][k8 + t];
            unsigned a1 = qs[w*16 + g + 8][k8 + t];
            unsigned a2 = qs[w*16 + g    ][k8 + t + 4];
            unsigned a3 = qs[w*16 + g + 8][k8 + t + 4];
            #pragma unroll
            for (int nt = 0; nt < 8; nt++) {
                unsigned b0 = ks[nt*8 + g][k8 + t];
                unsigned b1 = ks[nt*8 + g][k8 + t + 4];
                asm volatile(
                    "mma.sync.aligned.m16n8k8.row.col.f32.tf32.tf32.f32 "
                    "{%0,%1,%2,%3}, {%4,%5,%6,%7}, {%8,%9}, {%0,%1,%2,%3};"
                    : "+f"(s[nt][0]), "+f"(s[nt][1]), "+f"(s[nt][2]), "+f"(s[nt][3])
                    : "r"(a0), "r"(a1), "r"(a2), "r"(a3), "r"(b0), "r"(b1));
            }
        }

        float pm0 = NEG_INF, pm1 = NEG_INF;
        #pragma unroll
        for (int nt = 0; nt < 8; nt++) {
            int c0 = nt*8 + 2*t;
            bool k0 = msk[c0] != 0, k1 = msk[c0+1] != 0;
            s[nt][0] = k0 ? s[nt][0]*0.125f : NEG_INF;
            s[nt][1] = k1 ? s[nt][1]*0.125f : NEG_INF;
            s[nt][2] = k0 ? s[nt][2]*0.125f : NEG_INF;
            s[nt][3] = k1 ? s[nt][3]*0.125f : NEG_INF;
            pm0 = fmaxf(pm0, fmaxf(s[nt][0], s[nt][1]));
            pm1 = fmaxf(pm1, fmaxf(s[nt][2], s[nt][3]));
        }
        pm0 = fmaxf(pm0, __shfl_xor_sync(0xffffffffu, pm0, 1));
        pm0 = fmaxf(pm0, __shfl_xor_sync(0xffffffffu, pm0, 2));
        pm1 = fmaxf(pm1, __shfl_xor_sync(0xffffffffu, pm1, 1));
        pm1 = fmaxf(pm1, __shfl_xor_sync(0xffffffffu, pm1, 2));

        float mn0 = fmaxf(m0, pm0), mn1 = fmaxf(m1, pm1);
        float al0, al1, ps0 = 0.f, ps1 = 0.f;
        if (mn0 <= NEG_INF) {
            al0 = 1.f;
            #pragma unroll
            for (int nt = 0; nt < 8; nt++) { s[nt][0] = 0.f; s[nt][1] = 0.f; }
        } else {
            al0 = expf(m0 - mn0);
            #pragma unroll
            for (int nt = 0; nt < 8; nt++) {
                float p0 = expf(s[nt][0] - mn0), p1 = expf(s[nt][1] - mn0);
                s[nt][0] = p0; s[nt][1] = p1; ps0 += p0 + p1;
            }
        }
        if (mn1 <= NEG_INF) {
            al1 = 1.f;
            #pragma unroll
            for (int nt = 0; nt < 8; nt++) { s[nt][2] = 0.f; s[nt][3] = 0.f; }
        } else {
            al1 = expf(m1 - mn1);
            #pragma unroll
            for (int nt = 0; nt < 8; nt++) {
                float p2 = expf(s[nt][2] - mn1), p3 = expf(s[nt][3] - mn1);
                s[nt][2] = p2; s[nt][3] = p3; ps1 += p2 + p3;
            }
        }
        ps0 += __shfl_xor_sync(0xffffffffu, ps0, 1);
        ps0 += __shfl_xor_sync(0xffffffffu, ps0, 2);
        ps1 += __shfl_xor_sync(0xffffffffu, ps1, 1);
        ps1 += __shfl_xor_sync(0xffffffffu, ps1, 2);
        l0 = l0 * al0 + ps0; m0 = mn0;
        l1 = l1 * al1 + ps1; m1 = mn1;
        #pragma unroll
        for (int dt = 0; dt < 8; dt++) {
            o[dt][0] *= al0; o[dt][1] *= al0;
            o[dt][2] *= al1; o[dt][3] *= al1;
        }

        #pragma unroll
        for (int ki = 0; ki < 4; ki++) {
            unsigned a0 = packh2(s[2*ki  ][0], s[2*ki  ][1]);
            unsigned a1 = packh2(s[2*ki  ][2], s[2*ki  ][3]);
            unsigned a2 = packh2(s[2*ki+1][0], s[2*ki+1][1]);
            unsigned a3 = packh2(s[2*ki+1][2], s[2*ki+1][3]);
            #pragma unroll
            for (int dt = 0; dt < 8; dt++) {
                unsigned b0 = *(const unsigned*)&vs[dt*8 + g][ki*16 + 2*t];
                unsigned b1 = *(const unsigned*)&vs[dt*8 + g][ki*16 + 8 + 2*t];
                asm volatile(
                    "mma.sync.aligned.m16n8k16.row.col.f32.f16.f16.f32 "
                    "{%0,%1,%2,%3}, {%4,%5,%6,%7}, {%8,%9}, {%0,%1,%2,%3};"
                    : "+f"(o[dt][0]), "+f"(o[dt][1]), "+f"(o[dt][2]), "+f"(o[dt][3])
                    : "r"(a0), "r"(a1), "r"(a2), "r"(a3), "r"(b0), "r"(b1));
            }
        }
    }

    float il0 = (l0 > 0.f) ? 1.f/l0 : 0.f;
    float il1 = (l1 > 0.f) ? 1.f/l1 : 0.f;
    size_t r0 = (size_t)(b*SEQ + q0 + w*16 + g) * EMBED + h*HDIM;
    size_t r1 = r0 + (size_t)8 * EMBED;
    #pragma unroll
    for (int dt = 0; dt < 8; dt++) {
        int cc = dt*8 + 2*t;
        *(float2*)(g_attn + r0 + cc) = make_float2(o[dt][0]*il0, o[dt][1]*il0);
        *(float2*)(g_attn + r1 + cc) = make_float2(o[dt][2]*il1, o[dt][3]*il1);
    }
}

// ---------------- swiglu ---------------------------------------------------
__global__ void swiglu_kernel() {
    int idx = blockIdx.x * blockDim.x + threadIdx.x;
    int row = idx >> 10;
    int c4  = (idx & 1023) * 4;
    const float* base = g_h + (size_t)row * (2*MLPD);
    float4 a = *(const float4*)(base + c4);
    float4 g = *(const float4*)(base + MLPD + c4);
    float4 o;
    o.x = a.x / (1.f + expf(-a.x)) * g.x;
    o.y = a.y / (1.f + expf(-a.y)) * g.y;
    o.z = a.z / (1.f + expf(-a.z)) * g.z;
    o.w = a.w / (1.f + expf(-a.w)) * g.w;
    *(float4*)(g_hg + (size_t)row * MLPD + c4) = o;
}

// ------------------------------ launch ------------------------------------
static const int SIG_DECL[15] = {4194304,2048,4096,1024,1048576,1024,1048576,1024,
                                3145728,1048576,1024,8388608,8192,4194304,1024};
static const int SIG_ALPHA[15] = {4096,2048,8192,1024,8388608,4194304,1024,1024,
                                  1048576,3145728,1024,1048576,1024,1048576,4194304};
static const int MAP_ALPHA[15] = {14,1,0,6,11,10,13,12,9,8,7,4,2,5,3};

extern "C" void kernel_launch(void* const* d_in, const int* in_sizes, int n_in,
                              void* d_out, int out_size) {
    const void* in[15];
    bool decl_ok = (n_in >= 15), alpha_ok = (n_in >= 15);
    for (int i = 0; i < 15 && i < n_in; i++) {
        if (in_sizes[i] != SIG_DECL[i])  decl_ok = false;
        if (in_sizes[i] != SIG_ALPHA[i]) alpha_ok = false;
    }
    if (!decl_ok && alpha_ok) {
        for (int r = 0; r < 15; r++) in[r] = d_in[MAP_ALPHA[r]];
    } else {
        for (int r = 0; r < 15; r++) in[r] = d_in[r];
    }

    const float* x      = (const float*)in[0];
    const float* c      = (const float*)in[1];
    const int*   amask  = (const int*)  in[2];
    const float* norm_w = (const float*)in[3];
    const float* scale_w= (const float*)in[4];
    const float* scale_b= (const float*)in[5];
    const float* shift_w= (const float*)in[6];
    const float* shift_b= (const float*)in[7];
    const float* qkv_w  = (const float*)in[8];
    const float* proj_w = (const float*)in[9];
    const float* proj_b = (const float*)in[10];
    const float* mlp_w1 = (const float*)in[11];
    const float* mlp_b1 = (const float*)in[12];
    const float* mlp_w2 = (const float*)in[13];
    const float* mlp_b2 = (const float*)in[14];
    float* out = (float*)d_out;

    // raise dynamic-smem limits once per instantiation (host-side attr, capture-safe)
    static bool attr_done = false;
    if (!attr_done) {
        cudaFuncSetAttribute(tgemm_kernel<0,0,false,false,false>,
                             cudaFuncAttributeMaxDynamicSharedMemorySize, TGEMM_SMEM);
        cudaFuncSetAttribute(tgemm_kernel<1,1,true,true,false>,
                             cudaFuncAttributeMaxDynamicSharedMemorySize, TGEMM_SMEM);
        cudaFuncSetAttribute(tgemm_kernel<0,2,true,false,false>,
                             cudaFuncAttributeMaxDynamicSharedMemorySize, TGEMM_SMEM);
        cudaFuncSetAttribute(tgemm_kernel<2,3,true,false,true>,
                             cudaFuncAttributeMaxDynamicSharedMemorySize, TGEMM_SMEM);
        attr_done = true;
    }

    modvec_kernel<<<512, 256>>>(c, shift_w, shift_b, scale_w, scale_b);
    adaln_kernel<0><<<ROWS, 256>>>(x, norm_w);
    tgemm_kernel<0,0,false,false,false><<<dim3(3*EMBED/128, ROWS/128), 256, TGEMM_SMEM>>>(
        qkv_w, nullptr, nullptr, nullptr, ROWS, 3*EMBED, EMBED);
    attn_kernel<<<dim3(SEQ/64, HEADS, BATCH), 128>>>(amask);
    tgemm_kernel<1,1,true,true,false><<<dim3(EMBED/128, ROWS/128), 256, TGEMM_SMEM>>>(
        proj_w, proj_b, x, nullptr, ROWS, EMBED, EMBED);
    adaln_kernel<1><<<ROWS, 256>>>(nullptr, norm_w);
    tgemm_kernel<0,2,true,false,false><<<dim3(2*MLPD/128, ROWS/128), 256, TGEMM_SMEM>>>(
        mlp_w1, mlp_b1, nullptr, nullptr, ROWS, 2*MLPD, EMBED);
    swiglu_kernel<<<ROWS*(MLPD/4)/256, 256>>>();
    tgemm_kernel<2,3,true,false,true><<<dim3(EMBED/128, ROWS/128), 256, TGEMM_SMEM>>>(
        mlp_w2, mlp_b2, nullptr, out, ROWS, EMBED, MLPD);
}

// round 15
// speedup vs baseline: 10.6874x; 1.9646x over previous
#include <cuda_runtime.h>
#include <cuda_fp16.h>
#include <math.h>

#define BATCH 2
#define SEQ   2048
#define EMBED 1024
#define HEADS 16
#define HDIM  64
#define MLPD  4096
#define ROWS  (BATCH*SEQ)          // 4096
#define NEG_INF (-1e30f)

// ---------------- scratch (device globals; zero-init BSS; 16B-aligned) ----
__device__ __align__(16) float  g_shift[BATCH*EMBED];
__device__ __align__(16) float  g_scale[BATCH*EMBED];
__device__ __align__(16) float  g_x1  [ROWS*EMBED];        // residual stream (fp32)
__device__ __align__(16) float  g_h   [ROWS*2*MLPD];       // mlp1 out (fp32)
__device__ __align__(16) __half g_xa_h  [ROWS*EMBED];
__device__ __align__(16) __half g_qkv_h [ROWS*3*EMBED];
__device__ __align__(16) __half g_attn_h[ROWS*EMBED];
__device__ __align__(16) __half g_hg_h  [ROWS*MLPD];
__device__ __align__(16) __half g_qkvw_h[3*EMBED*EMBED];
__device__ __align__(16) __half g_projw_h[EMBED*EMBED];
__device__ __align__(16) __half g_w1_h  [2*MLPD*EMBED];
__device__ __align__(16) __half g_w2_h  [EMBED*MLPD];

__device__ __forceinline__ unsigned packh2(float lo, float hi) {
    __half2 h = __floats2half2_rn(lo, hi);
    return *reinterpret_cast<unsigned*>(&h);
}
__device__ __forceinline__ void cpasync16(unsigned dst, const void* src) {
    asm volatile("cp.async.cg.shared.global [%0], [%1], 16;" :: "r"(dst), "l"(src));
}
#define LDSM_X4(r0,r1,r2,r3,addr) \
    asm volatile("ldmatrix.sync.aligned.m8n8.x4.shared.b16 {%0,%1,%2,%3}, [%4];" \
        : "=r"(r0),"=r"(r1),"=r"(r2),"=r"(r3) : "r"(addr))
#define LDSM_X2(r0,r1,addr) \
    asm volatile("ldmatrix.sync.aligned.m8n8.x2.shared.b16 {%0,%1}, [%2];" \
        : "=r"(r0),"=r"(r1) : "r"(addr))
#define LDSM_X2T(r0,r1,addr) \
    asm volatile("ldmatrix.sync.aligned.m8n8.x2.trans.shared.b16 {%0,%1}, [%2];" \
        : "=r"(r0),"=r"(r1) : "r"(addr))
#define MMA16816(d0,d1,d2,d3,a0,a1,a2,a3,b0,b1) \
    asm volatile("mma.sync.aligned.m16n8k16.row.col.f32.f16.f16.f32 " \
        "{%0,%1,%2,%3}, {%4,%5,%6,%7}, {%8,%9}, {%0,%1,%2,%3};" \
        : "+f"(d0),"+f"(d1),"+f"(d2),"+f"(d3) \
        : "r"(a0),"r"(a1),"r"(a2),"r"(a3),"r"(b0),"r"(b1))

// ---------------- fp32 -> fp16 weight conversions (WSEL selects dst) ------
template<int WSEL>
__global__ void cvtw_kernel(const float4* __restrict__ s) {
    int i = blockIdx.x * blockDim.x + threadIdx.x;
    float4 v = s[i];
    uint2 p = make_uint2(packh2(v.x, v.y), packh2(v.z, v.w));
    uint2* d = (WSEL == 0) ? (uint2*)g_qkvw_h : (WSEL == 1) ? (uint2*)g_projw_h
             : (WSEL == 2) ? (uint2*)g_w1_h   : (uint2*)g_w2_h;
    d[i] = p;
}

// ---------------- adaLN modulation vectors -> g_shift / g_scale -----------
__global__ void modvec_kernel(const float* __restrict__ c,
                              const float* __restrict__ shift_w, const float* __restrict__ shift_b,
                              const float* __restrict__ scale_w, const float* __restrict__ scale_b) {
    int gw   = (blockIdx.x * blockDim.x + threadIdx.x) >> 5;
    int lane = threadIdx.x & 31;
    int which = gw >> 11;
    int b     = (gw >> 10) & 1;
    int j     = gw & 1023;
    const float* w  = (which ? scale_w : shift_w) + (size_t)j * EMBED;
    const float* cb = c + b * EMBED;
    float acc = 0.f;
    for (int k = lane; k < EMBED; k += 32) {
        float cv = cb[k];
        float s  = cv / (1.f + expf(-cv));
        acc += s * w[k];
    }
    #pragma unroll
    for (int off = 16; off; off >>= 1) acc += __shfl_xor_sync(0xffffffffu, acc, off);
    if (lane == 0) {
        if (which == 0) g_shift[b*EMBED + j] = acc + shift_b[j];
        else {
            float v = acc + scale_b[j] + 1.0f;
            g_scale[b*EMBED + j] = fminf(fmaxf(v, 0.1f), 10.0f);
        }
    }
}

// ---------------- RMS-norm + modulate -> g_xa_h (fp16) --------------------
template<int SRC>
__global__ void adaln_kernel(const float* __restrict__ xext, const float* __restrict__ norm_w) {
    int row = blockIdx.x;
    int b   = row >> 11;
    const float* xp = (SRC == 0) ? xext : g_x1;
    const float4* xr = (const float4*)(xp + (size_t)row * EMBED);
    float4 v = xr[threadIdx.x];
    float ss = v.x*v.x + v.y*v.y + v.z*v.z + v.w*v.w;
    __shared__ float red[8];
    #pragma unroll
    for (int off = 16; off; off >>= 1) ss += __shfl_xor_sync(0xffffffffu, ss, off);
    if ((threadIdx.x & 31) == 0) red[threadIdx.x >> 5] = ss;
    __syncthreads();
    __shared__ float s_inv;
    if (threadIdx.x == 0) {
        float t = 0.f;
        #pragma unroll
        for (int i = 0; i < 8; i++) t += red[i];
        float nrm = sqrtf(t) * (1.f / 32.f);
        s_inv = 1.f / fmaxf(nrm, 1e-6f);
    }
    __syncthreads();
    float inv = s_inv;
    const float4 nw = ((const float4*)norm_w)[threadIdx.x];
    const float4 sc = ((const float4*)(g_scale + (size_t)b*EMBED))[threadIdx.x];
    const float4 sh = ((const float4*)(g_shift + (size_t)b*EMBED))[threadIdx.x];
    float ox = v.x * inv * nw.x * sc.x + sh.x;
    float oy = v.y * inv * nw.y * sc.y + sh.y;
    float oz = v.z * inv * nw.z * sc.z + sh.z;
    float ow = v.w * inv * nw.w * sc.w + sh.w;
    *(uint2*)(g_xa_h + (size_t)row * EMBED + threadIdx.x * 4) =
        make_uint2(packh2(ox, oy), packh2(oz, ow));
}

// ---------------- fp16 tensor-core GEMM, ldmatrix + 2-stage cp.async ------
// C[m][n] = sum_k A[m][k]*Wsel[n][k] (+bias)(+res). CTA 128x128, BK=64,
// 256 thr (2Mx4N warps). A and W both selected IN-KERNEL by template params
// (no device-symbol addresses cross the host boundary).
// ASEL: 0=g_xa_h 1=g_attn_h 2=g_hg_h
// CSEL: 0=qkv (W=g_qkvw_h, half out)  1=proj (W=g_projw_h, ->g_x1)
//       2=mlp1 (W=g_w1_h, ->g_h)      3=mlp2 (W=g_w2_h, ->Cext)
#define HSK 72
#define TGSM_H (128*HSK)
template<int ASEL, int CSEL, bool BIAS, bool RESX, bool RESG>
__global__ __launch_bounds__(256)
void hgemm_kernel(const float* __restrict__ bias,
                  const float* __restrict__ resx, float* __restrict__ Cext,
                  int M, int Nn, int K) {
    const __half* A = (ASEL == 0) ? g_xa_h : (ASEL == 1) ? g_attn_h : g_hg_h;
    const __half* W = (CSEL == 0) ? g_qkvw_h : (CSEL == 1) ? g_projw_h
                    : (CSEL == 2) ? g_w1_h   : g_w2_h;

    extern __shared__ __align__(16) __half hsm[];
    unsigned sbase = (unsigned)__cvta_generic_to_shared(hsm);

    int tid  = threadIdx.x;
    int lane = tid & 31;
    int wid  = tid >> 5;
    int wm   = wid & 1;
    int wn   = wid >> 1;
    int g    = lane >> 2;
    int t    = lane & 3;
    int l15  = lane & 15, l16 = lane >> 4;
    int l7   = lane & 7,  l8  = (lane >> 3) & 1;

    int bm = blockIdx.y * 128, bn = blockIdx.x * 128;

    int cr[4], cq[4];
    #pragma unroll
    for (int it = 0; it < 4; it++) {
        int idx = it * 256 + tid;
        cr[it] = idx >> 3;
        cq[it] = (idx & 7) * 8;
    }

    float acc[4][4][4];
    #pragma unroll
    for (int i = 0; i < 4; i++)
        #pragma unroll
        for (int j = 0; j < 4; j++)
            #pragma unroll
            for (int r = 0; r < 4; r++) acc[i][j][r] = 0.f;

    const int NT = K >> 6;

    {
        #pragma unroll
        for (int it = 0; it < 4; it++) {
            cpasync16(sbase + 2*(cr[it]*HSK + cq[it]),
                      A + (size_t)(bm + cr[it]) * K + cq[it]);
            cpasync16(sbase + 2*(2*TGSM_H + cr[it]*HSK + cq[it]),
                      W + (size_t)(bn + cr[it]) * K + cq[it]);
        }
        asm volatile("cp.async.commit_group;");
    }

    for (int kt = 0; kt < NT; kt++) {
        asm volatile("cp.async.wait_group 0;" ::: "memory");
        __syncthreads();

        if (kt + 1 < NT) {
            int k0 = (kt + 1) << 6;
            unsigned offA = ((kt + 1) & 1) * TGSM_H;
            unsigned offB = 2*TGSM_H + offA;
            #pragma unroll
            for (int it = 0; it < 4; it++) {
                cpasync16(sbase + 2*(offA + cr[it]*HSK + cq[it]),
                          A + (size_t)(bm + cr[it]) * K + k0 + cq[it]);
                cpasync16(sbase + 2*(offB + cr[it]*HSK + cq[it]),
                          W + (size_t)(bn + cr[it]) * K + k0 + cq[it]);
            }
        }
        asm volatile("cp.async.commit_group;");

        unsigned aB = sbase + 2*((kt & 1) * TGSM_H);
        unsigned bB = sbase + 2*(2*TGSM_H + (kt & 1) * TGSM_H);

        #pragma unroll
        for (int ss = 0; ss < 4; ss++) {
            int kc = ss * 16;
            unsigned a[4][4], bf[4][2];
            #pragma unroll
            for (int mt = 0; mt < 4; mt++) {
                unsigned ad = aB + 2*((wm*64 + mt*16 + l15)*HSK + kc + l16*8);
                LDSM_X4(a[mt][0], a[mt][1], a[mt][2], a[mt][3], ad);
            }
            #pragma unroll
            for (int nt = 0; nt < 4; nt++) {
                unsigned bd = bB + 2*((wn*32 + nt*8 + l7)*HSK + kc + l8*8);
                LDSM_X2(bf[nt][0], bf[nt][1], bd);
            }
            #pragma unroll
            for (int mt = 0; mt < 4; mt++)
                #pragma unroll
                for (int nt = 0; nt < 4; nt++)
                    MMA16816(acc[mt][nt][0], acc[mt][nt][1], acc[mt][nt][2], acc[mt][nt][3],
                             a[mt][0], a[mt][1], a[mt][2], a[mt][3],
                             bf[nt][0], bf[nt][1]);
        }
    }

    #pragma unroll
    for (int mt = 0; mt < 4; mt++) {
        int r0 = bm + wm*64 + mt*16 + g;
        int r1 = r0 + 8;
        #pragma unroll
        for (int nt = 0; nt < 4; nt++) {
            int cc = bn + wn*32 + nt*8 + t*2;
            float v0 = acc[mt][nt][0], v1 = acc[mt][nt][1];
            float v2 = acc[mt][nt][2], v3 = acc[mt][nt][3];
            if (BIAS) { float b0 = bias[cc], b1 = bias[cc+1]; v0 += b0; v1 += b1; v2 += b0; v3 += b1; }
            if (RESX) {
                const float2 p0 = *(const float2*)(resx + (size_t)r0 * Nn + cc);
                const float2 p1 = *(const float2*)(resx + (size_t)r1 * Nn + cc);
                v0 += p0.x; v1 += p0.y; v2 += p1.x; v3 += p1.y;
            }
            if (RESG) {
                const float2 p0 = *(const float2*)(g_x1 + (size_t)r0 * Nn + cc);
                const float2 p1 = *(const float2*)(g_x1 + (size_t)r1 * Nn + cc);
                v0 += p0.x; v1 += p0.y; v2 += p1.x; v3 += p1.y;
            }
            if (CSEL == 0) {
                *(unsigned*)(g_qkv_h + (size_t)r0 * Nn + cc) = packh2(v0, v1);
                *(unsigned*)(g_qkv_h + (size_t)r1 * Nn + cc) = packh2(v2, v3);
            } else {
                float* C = (CSEL == 1) ? g_x1 : (CSEL == 2) ? g_h : Cext;
                *(float2*)(C + (size_t)r0 * Nn + cc) = make_float2(v0, v1);
                *(float2*)(C + (size_t)r1 * Nn + cc) = make_float2(v2, v3);
            }
        }
    }
}
#define TGEMM_SMEM (4*TGSM_H*(int)sizeof(__half))   // 73728 B

// ---------------- fp16 tensor-core flash attention -------------------------
// 64 q/block, 64-key tiles, 4 warps x 16 q-rows. QK^T and P.V: m16n8k16.
__global__ __launch_bounds__(128)
void attn_kernel(const int* __restrict__ mask) {
    __shared__ __align__(16) __half qs[64][HSK];
    __shared__ __align__(16) __half ks[64][HSK];
    __shared__ __align__(16) __half vs[64][HSK];   // natural [j][d]
    __shared__ int msk[64];

    int tid  = threadIdx.x;
    int lane = tid & 31, w = tid >> 5;
    int g = lane >> 2, t = lane & 3;
    int l15 = lane & 15;
    int l7 = lane & 7, l8 = (lane >> 3) & 1;
    int q0 = blockIdx.x * 64, h = blockIdx.y, b = blockIdx.z;

    unsigned qbase = (unsigned)__cvta_generic_to_shared(&qs[0][0]);
    unsigned kbase = (unsigned)__cvta_generic_to_shared(&ks[0][0]);
    unsigned vbase = (unsigned)__cvta_generic_to_shared(&vs[0][0]);

    for (int i = tid; i < 512; i += 128) {
        int r = i >> 3, c8 = (i & 7) * 8;
        *(uint4*)&qs[r][c8] =
            *(const uint4*)(g_qkv_h + (size_t)(b*SEQ + q0 + r)*3072 + h*HDIM + c8);
    }
    __syncthreads();
    unsigned aq[4][4];
    #pragma unroll
    for (int ss = 0; ss < 4; ss++) {
        unsigned ad = qbase + 2*((w*16 + l15)*HSK + ss*16 + (lane>>4)*8);
        LDSM_X4(aq[ss][0], aq[ss][1], aq[ss][2], aq[ss][3], ad);
    }

    float m0 = NEG_INF, m1 = NEG_INF, l0 = 0.f, l1 = 0.f;
    float o[8][4];
    #pragma unroll
    for (int dt = 0; dt < 8; dt++)
        #pragma unroll
        for (int r = 0; r < 4; r++) o[dt][r] = 0.f;

    for (int kt = 0; kt < SEQ/64; kt++) {
        __syncthreads();
        for (int i = tid; i < 1024; i += 128) {
            int which = i >> 9;
            int j = i & 511;
            int r = j >> 3, c8 = (j & 7) * 8;
            uint4 val = *(const uint4*)(g_qkv_h + (size_t)(b*SEQ + kt*64 + r)*3072
                                        + h*HDIM + 1024 + which*1024 + c8);
            if (which == 0) *(uint4*)&ks[r][c8] = val;
            else            *(uint4*)&vs[r][c8] = val;
        }
        if (tid < 64) msk[tid] = mask[b*SEQ + kt*64 + tid];
        __syncthreads();

        float s[8][4];
        #pragma unroll
        for (int nt = 0; nt < 8; nt++)
            #pragma unroll
            for (int r = 0; r < 4; r++) s[nt][r] = 0.f;

        #pragma unroll
        for (int ss = 0; ss < 4; ss++) {
            int kc = ss * 16;
            #pragma unroll
            for (int nt = 0; nt < 8; nt++) {
                unsigned b0, b1;
                unsigned bd = kbase + 2*((nt*8 + l7)*HSK + kc + l8*8);
                LDSM_X2(b0, b1, bd);
                MMA16816(s[nt][0], s[nt][1], s[nt][2], s[nt][3],
                         aq[ss][0], aq[ss][1], aq[ss][2], aq[ss][3], b0, b1);
            }
        }

        float pm0 = NEG_INF, pm1 = NEG_INF;
        #pragma unroll
        for (int nt = 0; nt < 8; nt++) {
            int c0 = nt*8 + 2*t;
            bool k0 = msk[c0] != 0, k1 = msk[c0+1] != 0;
            s[nt][0] = k0 ? s[nt][0]*0.125f : NEG_INF;
            s[nt][1] = k1 ? s[nt][1]*0.125f : NEG_INF;
            s[nt][2] = k0 ? s[nt][2]*0.125f : NEG_INF;
            s[nt][3] = k1 ? s[nt][3]*0.125f : NEG_INF;
            pm0 = fmaxf(pm0, fmaxf(s[nt][0], s[nt][1]));
            pm1 = fmaxf(pm1, fmaxf(s[nt][2], s[nt][3]));
        }
        pm0 = fmaxf(pm0, __shfl_xor_sync(0xffffffffu, pm0, 1));
        pm0 = fmaxf(pm0, __shfl_xor_sync(0xffffffffu, pm0, 2));
        pm1 = fmaxf(pm1, __shfl_xor_sync(0xffffffffu, pm1, 1));
        pm1 = fmaxf(pm1, __shfl_xor_sync(0xffffffffu, pm1, 2));

        float mn0 = fmaxf(m0, pm0), mn1 = fmaxf(m1, pm1);
        float al0, al1, ps0 = 0.f, ps1 = 0.f;
        if (mn0 <= NEG_INF) {
            al0 = 1.f;
            #pragma unroll
            for (int nt = 0; nt < 8; nt++) { s[nt][0] = 0.f; s[nt][1] = 0.f; }
        } else {
            al0 = expf(m0 - mn0);
            #pragma unroll
            for (int nt = 0; nt < 8; nt++) {
                float p0 = expf(s[nt][0] - mn0), p1 = expf(s[nt][1] - mn0);
                s[nt][0] = p0; s[nt][1] = p1; ps0 += p0 + p1;
            }
        }
        if (mn1 <= NEG_INF) {
            al1 = 1.f;
            #pragma unroll
            for (int nt = 0; nt < 8; nt++) { s[nt][2] = 0.f; s[nt][3] = 0.f; }
        } else {
            al1 = expf(m1 - mn1);
            #pragma unroll
            for (int nt = 0; nt < 8; nt++) {
                float p2 = expf(s[nt][2] - mn1), p3 = expf(s[nt][3] - mn1);
                s[nt][2] = p2; s[nt][3] = p3; ps1 += p2 + p3;
            }
        }
        ps0 += __shfl_xor_sync(0xffffffffu, ps0, 1);
        ps0 += __shfl_xor_sync(0xffffffffu, ps0, 2);
        ps1 += __shfl_xor_sync(0xffffffffu, ps1, 1);
        ps1 += __shfl_xor_sync(0xffffffffu, ps1, 2);
        l0 = l0 * al0 + ps0; m0 = mn0;
        l1 = l1 * al1 + ps1; m1 = mn1;
        #pragma unroll
        for (int dt = 0; dt < 8; dt++) {
            o[dt][0] *= al0; o[dt][1] *= al0;
            o[dt][2] *= al1; o[dt][3] *= al1;
        }

        #pragma unroll
        for (int ki = 0; ki < 4; ki++) {
            unsigned a0 = packh2(s[2*ki  ][0], s[2*ki  ][1]);
            unsigned a1 = packh2(s[2*ki  ][2], s[2*ki  ][3]);
            unsigned a2 = packh2(s[2*ki+1][0], s[2*ki+1][1]);
            unsigned a3 = packh2(s[2*ki+1][2], s[2*ki+1][3]);
            #pragma unroll
            for (int dt = 0; dt < 8; dt++) {
                unsigned b0, b1;
                unsigned vd = vbase + 2*((ki*16 + l15)*HSK + dt*8);
                LDSM_X2T(b0, b1, vd);
                MMA16816(o[dt][0], o[dt][1], o[dt][2], o[dt][3],
                         a0, a1, a2, a3, b0, b1);
            }
        }
    }

    float il0 = (l0 > 0.f) ? 1.f/l0 : 0.f;
    float il1 = (l1 > 0.f) ? 1.f/l1 : 0.f;
    size_t r0 = (size_t)(b*SEQ + q0 + w*16 + g) * EMBED + h*HDIM;
    size_t r1 = r0 + (size_t)8 * EMBED;
    #pragma unroll
    for (int dt = 0; dt < 8; dt++) {
        int cc = dt*8 + 2*t;
        *(unsigned*)(g_attn_h + r0 + cc) = packh2(o[dt][0]*il0, o[dt][1]*il0);
        *(unsigned*)(g_attn_h + r1 + cc) = packh2(o[dt][2]*il1, o[dt][3]*il1);
    }
}

// ---------------- swiglu -> fp16 ------------------------------------------
__global__ void swiglu_kernel() {
    int idx = blockIdx.x * blockDim.x + threadIdx.x;
    int row = idx >> 10;
    int c4  = (idx & 1023) * 4;
    const float* base = g_h + (size_t)row * (2*MLPD);
    float4 a = *(const float4*)(base + c4);
    float4 g = *(const float4*)(base + MLPD + c4);
    float ox = a.x / (1.f + expf(-a.x)) * g.x;
    float oy = a.y / (1.f + expf(-a.y)) * g.y;
    float oz = a.z / (1.f + expf(-a.z)) * g.z;
    float ow = a.w / (1.f + expf(-a.w)) * g.w;
    *(uint2*)(g_hg_h + (size_t)row * MLPD + c4) = make_uint2(packh2(ox, oy), packh2(oz, ow));
}

// ------------------------------ launch ------------------------------------
static const int SIG_DECL[15] = {4194304,2048,4096,1024,1048576,1024,1048576,1024,
                                3145728,1048576,1024,8388608,8192,4194304,1024};
static const int SIG_ALPHA[15] = {4096,2048,8192,1024,8388608,4194304,1024,1024,
                                  1048576,3145728,1024,1048576,1024,1048576,4194304};
static const int MAP_ALPHA[15] = {14,1,0,6,11,10,13,12,9,8,7,4,2,5,3};

extern "C" void kernel_launch(void* const* d_in, const int* in_sizes, int n_in,
                              void* d_out, int out_size) {
    const void* in[15];
    bool decl_ok = (n_in >= 15), alpha_ok = (n_in >= 15);
    for (int i = 0; i < 15 && i < n_in; i++) {
        if (in_sizes[i] != SIG_DECL[i])  decl_ok = false;
        if (in_sizes[i] != SIG_ALPHA[i]) alpha_ok = false;
    }
    if (!decl_ok && alpha_ok) {
        for (int r = 0; r < 15; r++) in[r] = d_in[MAP_ALPHA[r]];
    } else {
        for (int r = 0; r < 15; r++) in[r] = d_in[r];
    }

    const float* x      = (const float*)in[0];
    const float* c      = (const float*)in[1];
    const int*   amask  = (const int*)  in[2];
    const float* norm_w = (const float*)in[3];
    const float* scale_w= (const float*)in[4];
    const float* scale_b= (const float*)in[5];
    const float* shift_w= (const float*)in[6];
    const float* shift_b= (const float*)in[7];
    const float* qkv_w  = (const float*)in[8];
    const float* proj_w = (const float*)in[9];
    const float* proj_b = (const float*)in[10];
    const float* mlp_w1 = (const float*)in[11];
    const float* mlp_b1 = (const float*)in[12];
    const float* mlp_w2 = (const float*)in[13];
    const float* mlp_b2 = (const float*)in[14];
    float* out = (float*)d_out;

    static bool attr_done = false;
    if (!attr_done) {
        cudaFuncSetAttribute(hgemm_kernel<0,0,false,false,false>,
                             cudaFuncAttributeMaxDynamicSharedMemorySize, TGEMM_SMEM);
        cudaFuncSetAttribute(hgemm_kernel<1,1,true,true,false>,
                             cudaFuncAttributeMaxDynamicSharedMemorySize, TGEMM_SMEM);
        cudaFuncSetAttribute(hgemm_kernel<0,2,true,false,false>,
                             cudaFuncAttributeMaxDynamicSharedMemorySize, TGEMM_SMEM);
        cudaFuncSetAttribute(hgemm_kernel<2,3,true,false,true>,
                             cudaFuncAttributeMaxDynamicSharedMemorySize, TGEMM_SMEM);
        attr_done = true;
    }

    // weight conversions (run every launch; deterministic)
    cvtw_kernel<0><<<3*EMBED*EMBED/4/256, 256>>>((const float4*)qkv_w);
    cvtw_kernel<1><<<EMBED*EMBED/4/256, 256>>>((const float4*)proj_w);
    cvtw_kernel<2><<<2*MLPD*EMBED/4/256, 256>>>((const float4*)mlp_w1);
    cvtw_kernel<3><<<EMBED*MLPD/4/256, 256>>>((const float4*)mlp_w2);

    modvec_kernel<<<512, 256>>>(c, shift_w, shift_b, scale_w, scale_b);
    adaln_kernel<0><<<ROWS, 256>>>(x, norm_w);
    hgemm_kernel<0,0,false,false,false><<<dim3(3*EMBED/128, ROWS/128), 256, TGEMM_SMEM>>>(
        nullptr, nullptr, nullptr, ROWS, 3*EMBED, EMBED);
    attn_kernel<<<dim3(SEQ/64, HEADS, BATCH), 128>>>(amask);
    hgemm_kernel<1,1,true,true,false><<<dim3(EMBED/128, ROWS/128), 256, TGEMM_SMEM>>>(
        proj_b, x, nullptr, ROWS, EMBED, EMBED);
    adaln_kernel<1><<<ROWS, 256>>>(nullptr, norm_w);
    hgemm_kernel<0,2,true,false,false><<<dim3(2*MLPD/128, ROWS/128), 256, TGEMM_SMEM>>>(
        mlp_b1, nullptr, nullptr, ROWS, 2*MLPD, EMBED);
    swiglu_kernel<<<ROWS*(MLPD/4)/256, 256>>>();
    hgemm_kernel<2,3,true,false,true><<<dim3(EMBED/128, ROWS/128), 256, TGEMM_SMEM>>>(
        mlp_b2, nullptr, out, ROWS, EMBED, MLPD);
}

// round 17
// speedup vs baseline: 11.1251x; 1.0410x over previous
#include <cuda_runtime.h>
#include <cuda_fp16.h>
#include <math.h>

#define BATCH 2
#define SEQ   2048
#define EMBED 1024
#define HEADS 16
#define HDIM  64
#define MLPD  4096
#define ROWS  (BATCH*SEQ)          // 4096
#define NEG_INF (-1e30f)

// ---------------- scratch (device globals; zero-init BSS; 16B-aligned) ----
__device__ __align__(16) float  g_shift[BATCH*EMBED];
__device__ __align__(16) float  g_scale[BATCH*EMBED];
__device__ __align__(16) float  g_x1  [ROWS*EMBED];        // residual stream (fp32)
__device__ __align__(16) __half g_h_h [ROWS*2*MLPD];       // mlp1 out (fp16)
__device__ __align__(16) __half g_xa_h  [ROWS*EMBED];
__device__ __align__(16) __half g_qkv_h [ROWS*3*EMBED];
__device__ __align__(16) __half g_attn_h[ROWS*EMBED];
__device__ __align__(16) __half g_hg_h  [ROWS*MLPD];
__device__ __align__(16) __half g_qkvw_h[3*EMBED*EMBED];
__device__ __align__(16) __half g_projw_h[EMBED*EMBED];
__device__ __align__(16) __half g_w1_h  [2*MLPD*EMBED];
__device__ __align__(16) __half g_w2_h  [EMBED*MLPD];

__device__ __forceinline__ unsigned packh2(float lo, float hi) {
    __half2 h = __floats2half2_rn(lo, hi);
    return *reinterpret_cast<unsigned*>(&h);
}
__device__ __forceinline__ void cpasync16(unsigned dst, const void* src) {
    asm volatile("cp.async.cg.shared.global [%0], [%1], 16;" :: "r"(dst), "l"(src));
}
#define LDSM_X4(r0,r1,r2,r3,addr) \
    asm volatile("ldmatrix.sync.aligned.m8n8.x4.shared.b16 {%0,%1,%2,%3}, [%4];" \
        : "=r"(r0),"=r"(r1),"=r"(r2),"=r"(r3) : "r"(addr))
#define LDSM_X2(r0,r1,addr) \
    asm volatile("ldmatrix.sync.aligned.m8n8.x2.shared.b16 {%0,%1}, [%2];" \
        : "=r"(r0),"=r"(r1) : "r"(addr))
#define LDSM_X2T(r0,r1,addr) \
    asm volatile("ldmatrix.sync.aligned.m8n8.x2.trans.shared.b16 {%0,%1}, [%2];" \
        : "=r"(r0),"=r"(r1) : "r"(addr))
#define MMA16816(d0,d1,d2,d3,a0,a1,a2,a3,b0,b1) \
    asm volatile("mma.sync.aligned.m16n8k16.row.col.f32.f16.f16.f32 " \
        "{%0,%1,%2,%3}, {%4,%5,%6,%7}, {%8,%9}, {%0,%1,%2,%3};" \
        : "+f"(d0),"+f"(d1),"+f"(d2),"+f"(d3) \
        : "r"(a0),"r"(a1),"r"(a2),"r"(a3),"r"(b0),"r"(b1))

// ---------------- fp32 -> fp16 weight conversions (WSEL selects dst) ------
template<int WSEL>
__global__ void cvtw_kernel(const float4* __restrict__ s) {
    int i = blockIdx.x * blockDim.x + threadIdx.x;
    float4 v = s[i];
    uint2 p = make_uint2(packh2(v.x, v.y), packh2(v.z, v.w));
    uint2* d = (WSEL == 0) ? (uint2*)g_qkvw_h : (WSEL == 1) ? (uint2*)g_projw_h
             : (WSEL == 2) ? (uint2*)g_w1_h   : (uint2*)g_w2_h;
    d[i] = p;
}

// ---------------- adaLN modulation vectors -> g_shift / g_scale -----------
__global__ void modvec_kernel(const float* __restrict__ c,
                              const float* __restrict__ shift_w, const float* __restrict__ shift_b,
                              const float* __restrict__ scale_w, const float* __restrict__ scale_b) {
    int gw   = (blockIdx.x * blockDim.x + threadIdx.x) >> 5;
    int lane = threadIdx.x & 31;
    int which = gw >> 11;
    int b     = (gw >> 10) & 1;
    int j     = gw & 1023;
    const float* w  = (which ? scale_w : shift_w) + (size_t)j * EMBED;
    const float* cb = c + b * EMBED;
    float acc = 0.f;
    for (int k = lane; k < EMBED; k += 32) {
        float cv = cb[k];
        float s  = cv / (1.f + expf(-cv));
        acc += s * w[k];
    }
    #pragma unroll
    for (int off = 16; off; off >>= 1) acc += __shfl_xor_sync(0xffffffffu, acc, off);
    if (lane == 0) {
        if (which == 0) g_shift[b*EMBED + j] = acc + shift_b[j];
        else {
            float v = acc + scale_b[j] + 1.0f;
            g_scale[b*EMBED + j] = fminf(fmaxf(v, 0.1f), 10.0f);
        }
    }
}

// ---------------- RMS-norm + modulate -> g_xa_h (fp16) --------------------
template<int SRC>
__global__ void adaln_kernel(const float* __restrict__ xext, const float* __restrict__ norm_w) {
    int row = blockIdx.x;
    int b   = row >> 11;
    const float* xp = (SRC == 0) ? xext : g_x1;
    const float4* xr = (const float4*)(xp + (size_t)row * EMBED);
    float4 v = xr[threadIdx.x];
    float ss = v.x*v.x + v.y*v.y + v.z*v.z + v.w*v.w;
    __shared__ float red[8];
    #pragma unroll
    for (int off = 16; off; off >>= 1) ss += __shfl_xor_sync(0xffffffffu, ss, off);
    if ((threadIdx.x & 31) == 0) red[threadIdx.x >> 5] = ss;
    __syncthreads();
    __shared__ float s_inv;
    if (threadIdx.x == 0) {
        float t = 0.f;
        #pragma unroll
        for (int i = 0; i < 8; i++) t += red[i];
        float nrm = sqrtf(t) * (1.f / 32.f);
        s_inv = 1.f / fmaxf(nrm, 1e-6f);
    }
    __syncthreads();
    float inv = s_inv;
    const float4 nw = ((const float4*)norm_w)[threadIdx.x];
    const float4 sc = ((const float4*)(g_scale + (size_t)b*EMBED))[threadIdx.x];
    const float4 sh = ((const float4*)(g_shift + (size_t)b*EMBED))[threadIdx.x];
    float ox = v.x * inv * nw.x * sc.x + sh.x;
    float oy = v.y * inv * nw.y * sc.y + sh.y;
    float oz = v.z * inv * nw.z * sc.z + sh.z;
    float ow = v.w * inv * nw.w * sc.w + sh.w;
    *(uint2*)(g_xa_h + (size_t)row * EMBED + threadIdx.x * 4) =
        make_uint2(packh2(ox, oy), packh2(oz, ow));
}

// ---------------- fp16 tensor-core GEMM, ldmatrix + 2-stage cp.async ------
// ASEL: 0=g_xa_h 1=g_attn_h 2=g_hg_h
// CSEL: 0=qkv (W=g_qkvw_h, ->g_qkv_h half)  1=proj (W=g_projw_h, ->g_x1 f32)
//       2=mlp1 (W=g_w1_h, ->g_h_h half)     3=mlp2 (W=g_w2_h, ->Cext f32)
#define HSK 72
#define TGSM_H (128*HSK)
template<int ASEL, int CSEL, bool BIAS, bool RESX, bool RESG>
__global__ __launch_bounds__(256)
void hgemm_kernel(const float* __restrict__ bias,
                  const float* __restrict__ resx, float* __restrict__ Cext,
                  int M, int Nn, int K) {
    const __half* A = (ASEL == 0) ? g_xa_h : (ASEL == 1) ? g_attn_h : g_hg_h;
    const __half* W = (CSEL == 0) ? g_qkvw_h : (CSEL == 1) ? g_projw_h
                    : (CSEL == 2) ? g_w1_h   : g_w2_h;

    extern __shared__ __align__(16) __half hsm[];
    unsigned sbase = (unsigned)__cvta_generic_to_shared(hsm);

    int tid  = threadIdx.x;
    int lane = tid & 31;
    int wid  = tid >> 5;
    int wm   = wid & 1;
    int wn   = wid >> 1;
    int g    = lane >> 2;
    int t    = lane & 3;
    int l15  = lane & 15, l16 = lane >> 4;
    int l7   = lane & 7,  l8  = (lane >> 3) & 1;

    int bm = blockIdx.y * 128, bn = blockIdx.x * 128;

    int cr[4], cq[4];
    #pragma unroll
    for (int it = 0; it < 4; it++) {
        int idx = it * 256 + tid;
        cr[it] = idx >> 3;
        cq[it] = (idx & 7) * 8;
    }

    float acc[4][4][4];
    #pragma unroll
    for (int i = 0; i < 4; i++)
        #pragma unroll
        for (int j = 0; j < 4; j++)
            #pragma unroll
            for (int r = 0; r < 4; r++) acc[i][j][r] = 0.f;

    const int NT = K >> 6;

    {
        #pragma unroll
        for (int it = 0; it < 4; it++) {
            cpasync16(sbase + 2*(cr[it]*HSK + cq[it]),
                      A + (size_t)(bm + cr[it]) * K + cq[it]);
            cpasync16(sbase + 2*(2*TGSM_H + cr[it]*HSK + cq[it]),
                      W + (size_t)(bn + cr[it]) * K + cq[it]);
        }
        asm volatile("cp.async.commit_group;");
    }

    for (int kt = 0; kt < NT; kt++) {
        asm volatile("cp.async.wait_group 0;" ::: "memory");
        __syncthreads();

        if (kt + 1 < NT) {
            int k0 = (kt + 1) << 6;
            unsigned offA = ((kt + 1) & 1) * TGSM_H;
            unsigned offB = 2*TGSM_H + offA;
            #pragma unroll
            for (int it = 0; it < 4; it++) {
                cpasync16(sbase + 2*(offA + cr[it]*HSK + cq[it]),
                          A + (size_t)(bm + cr[it]) * K + k0 + cq[it]);
                cpasync16(sbase + 2*(offB + cr[it]*HSK + cq[it]),
                          W + (size_t)(bn + cr[it]) * K + k0 + cq[it]);
            }
        }
        asm volatile("cp.async.commit_group;");

        unsigned aB = sbase + 2*((kt & 1) * TGSM_H);
        unsigned bB = sbase + 2*(2*TGSM_H + (kt & 1) * TGSM_H);

        #pragma unroll
        for (int ss = 0; ss < 4; ss++) {
            int kc = ss * 16;
            unsigned a[4][4], bf[4][2];
            #pragma unroll
            for (int mt = 0; mt < 4; mt++) {
                unsigned ad = aB + 2*((wm*64 + mt*16 + l15)*HSK + kc + l16*8);
                LDSM_X4(a[mt][0], a[mt][1], a[mt][2], a[mt][3], ad);
            }
            #pragma unroll
            for (int nt = 0; nt < 4; nt++) {
                unsigned bd = bB + 2*((wn*32 + nt*8 + l7)*HSK + kc + l8*8);
                LDSM_X2(bf[nt][0], bf[nt][1], bd);
            }
            #pragma unroll
            for (int mt = 0; mt < 4; mt++)
                #pragma unroll
                for (int nt = 0; nt < 4; nt++)
                    MMA16816(acc[mt][nt][0], acc[mt][nt][1], acc[mt][nt][2], acc[mt][nt][3],
                             a[mt][0], a[mt][1], a[mt][2], a[mt][3],
                             bf[nt][0], bf[nt][1]);
        }
    }

    #pragma unroll
    for (int mt = 0; mt < 4; mt++) {
        int r0 = bm + wm*64 + mt*16 + g;
        int r1 = r0 + 8;
        #pragma unroll
        for (int nt = 0; nt < 4; nt++) {
            int cc = bn + wn*32 + nt*8 + t*2;
            float v0 = acc[mt][nt][0], v1 = acc[mt][nt][1];
            float v2 = acc[mt][nt][2], v3 = acc[mt][nt][3];
            if (BIAS) { float b0 = bias[cc], b1 = bias[cc+1]; v0 += b0; v1 += b1; v2 += b0; v3 += b1; }
            if (RESX) {
                const float2 p0 = *(const float2*)(resx + (size_t)r0 * Nn + cc);
                const float2 p1 = *(const float2*)(resx + (size_t)r1 * Nn + cc);
                v0 += p0.x; v1 += p0.y; v2 += p1.x; v3 += p1.y;
            }
            if (RESG) {
                const float2 p0 = *(const float2*)(g_x1 + (size_t)r0 * Nn + cc);
                const float2 p1 = *(const float2*)(g_x1 + (size_t)r1 * Nn + cc);
                v0 += p0.x; v1 += p0.y; v2 += p1.x; v3 += p1.y;
            }
            if (CSEL == 0) {
                *(unsigned*)(g_qkv_h + (size_t)r0 * Nn + cc) = packh2(v0, v1);
                *(unsigned*)(g_qkv_h + (size_t)r1 * Nn + cc) = packh2(v2, v3);
            } else if (CSEL == 2) {
                *(unsigned*)(g_h_h + (size_t)r0 * Nn + cc) = packh2(v0, v1);
                *(unsigned*)(g_h_h + (size_t)r1 * Nn + cc) = packh2(v2, v3);
            } else {
                float* C = (CSEL == 1) ? g_x1 : Cext;
                *(float2*)(C + (size_t)r0 * Nn + cc) = make_float2(v0, v1);
                *(float2*)(C + (size_t)r1 * Nn + cc) = make_float2(v2, v3);
            }
        }
    }
}
#define TGEMM_SMEM (4*TGSM_H*(int)sizeof(__half))   // 73728 B

// ---------------- fp16 flash attention, cp.async double-buffered KV --------
// 64 q/block, 64-key tiles, 4 warps x 16 q-rows.
__global__ __launch_bounds__(128)
void attn_kernel(const int* __restrict__ mask) {
    __shared__ __align__(16) __half qs[64][HSK];
    __shared__ __align__(16) __half ks[2][64][HSK];
    __shared__ __align__(16) __half vs[2][64][HSK];
    __shared__ __align__(16) int    msk[2][64];

    int tid  = threadIdx.x;
    int lane = tid & 31, w = tid >> 5;
    int g = lane >> 2, t = lane & 3;
    int l15 = lane & 15;
    int l7 = lane & 7, l8 = (lane >> 3) & 1;
    int q0 = blockIdx.x * 64, h = blockIdx.y, b = blockIdx.z;

    unsigned qbase = (unsigned)__cvta_generic_to_shared(&qs[0][0]);
    unsigned kbase0 = (unsigned)__cvta_generic_to_shared(&ks[0][0][0]);
    unsigned vbase0 = (unsigned)__cvta_generic_to_shared(&vs[0][0][0]);
    unsigned mbase0 = (unsigned)__cvta_generic_to_shared(&msk[0][0]);
    const unsigned KVSTRIDE = 64*HSK*2;     // bytes per KV buffer

    // issue KV tile 0 (cp.async) while loading Q with plain loads
    {
        // K,V: 1024 16B-chunks total, 8 per thread
        #pragma unroll
        for (int it = 0; it < 8; it++) {
            int i = it * 128 + tid;
            int which = i >> 9;            // 0=K 1=V
            int j = i & 511;
            int r = j >> 3, c8 = (j & 7) * 8;
            const void* src = g_qkv_h + (size_t)(b*SEQ + r)*3072
                              + h*HDIM + 1024 + which*1024 + c8;
            unsigned dst = (which ? vbase0 : kbase0) + 2*(r*HSK + c8);
            cpasync16(dst, src);
        }
        if (tid < 16) {
            cpasync16(mbase0 + tid*16, mask + b*SEQ + tid*4);
        }
        asm volatile("cp.async.commit_group;");
    }

    for (int i = tid; i < 512; i += 128) {
        int r = i >> 3, c8 = (i & 7) * 8;
        *(uint4*)&qs[r][c8] =
            *(const uint4*)(g_qkv_h + (size_t)(b*SEQ + q0 + r)*3072 + h*HDIM + c8);
    }
    __syncthreads();
    unsigned aq[4][4];
    #pragma unroll
    for (int ss = 0; ss < 4; ss++) {
        unsigned ad = qbase + 2*((w*16 + l15)*HSK + ss*16 + (lane>>4)*8);
        LDSM_X4(aq[ss][0], aq[ss][1], aq[ss][2], aq[ss][3], ad);
    }

    float m0 = NEG_INF, m1 = NEG_INF, l0 = 0.f, l1 = 0.f;
    float o[8][4];
    #pragma unroll
    for (int dt = 0; dt < 8; dt++)
        #pragma unroll
        for (int r = 0; r < 4; r++) o[dt][r] = 0.f;

    const int NT = SEQ/64;
    for (int kt = 0; kt < NT; kt++) {
        int buf = kt & 1;
        asm volatile("cp.async.wait_group 0;" ::: "memory");
        __syncthreads();

        if (kt + 1 < NT) {
            int nb = buf ^ 1;
            unsigned koff = kbase0 + nb*KVSTRIDE;
            unsigned voff = vbase0 + nb*KVSTRIDE;
            #pragma unroll
            for (int it = 0; it < 8; it++) {
                int i = it * 128 + tid;
                int which = i >> 9;
                int j = i & 511;
                int r = j >> 3, c8 = (j & 7) * 8;
                const void* src = g_qkv_h + (size_t)(b*SEQ + (kt+1)*64 + r)*3072
                                  + h*HDIM + 1024 + which*1024 + c8;
                unsigned dst = (which ? voff : koff) + 2*(r*HSK + c8);
                cpasync16(dst, src);
            }
            if (tid < 16) {
                cpasync16(mbase0 + nb*256 + tid*16, mask + b*SEQ + (kt+1)*64 + tid*4);
            }
        }
        asm volatile("cp.async.commit_group;");

        unsigned kbase = kbase0 + buf*KVSTRIDE;
        unsigned vbase = vbase0 + buf*KVSTRIDE;
        const int* mk = msk[buf];

        float s[8][4];
        #pragma unroll
        for (int nt = 0; nt < 8; nt++)
            #pragma unroll
            for (int r = 0; r < 4; r++) s[nt][r] = 0.f;

        #pragma unroll
        for (int ss = 0; ss < 4; ss++) {
            int kc = ss * 16;
            #pragma unroll
            for (int nt = 0; nt < 8; nt++) {
                unsigned b0, b1;
                unsigned bd = kbase + 2*((nt*8 + l7)*HSK + kc + l8*8);
                LDSM_X2(b0, b1, bd);
                MMA16816(s[nt][0], s[nt][1], s[nt][2], s[nt][3],
                         aq[ss][0], aq[ss][1], aq[ss][2], aq[ss][3], b0, b1);
            }
        }

        float pm0 = NEG_INF, pm1 = NEG_INF;
        #pragma unroll
        for (int nt = 0; nt < 8; nt++) {
            int c0 = nt*8 + 2*t;
            bool k0 = mk[c0] != 0, k1 = mk[c0+1] != 0;
            s[nt][0] = k0 ? s[nt][0]*0.125f : NEG_INF;
            s[nt][1] = k1 ? s[nt][1]*0.125f : NEG_INF;
            s[nt][2] = k0 ? s[nt][2]*0.125f : NEG_INF;
            s[nt][3] = k1 ? s[nt][3]*0.125f : NEG_INF;
            pm0 = fmaxf(pm0, fmaxf(s[nt][0], s[nt][1]));
            pm1 = fmaxf(pm1, fmaxf(s[nt][2], s[nt][3]));
        }
        pm0 = fmaxf(pm0, __shfl_xor_sync(0xffffffffu, pm0, 1));
        pm0 = fmaxf(pm0, __shfl_xor_sync(0xffffffffu, pm0, 2));
        pm1 = fmaxf(pm1, __shfl_xor_sync(0xffffffffu, pm1, 1));
        pm1 = fmaxf(pm1, __shfl_xor_sync(0xffffffffu, pm1, 2));

        float mn0 = fmaxf(m0, pm0), mn1 = fmaxf(m1, pm1);
        float al0, al1, ps0 = 0.f, ps1 = 0.f;
        if (mn0 <= NEG_INF) {
            al0 = 1.f;
            #pragma unroll
            for (int nt = 0; nt < 8; nt++) { s[nt][0] = 0.f; s[nt][1] = 0.f; }
        } else {
            al0 = expf(m0 - mn0);
            #pragma unroll
            for (int nt = 0; nt < 8; nt++) {
                float p0 = expf(s[nt][0] - mn0), p1 = expf(s[nt][1] - mn0);
                s[nt][0] = p0; s[nt][1] = p1; ps0 += p0 + p1;
            }
        }
        if (mn1 <= NEG_INF) {
            al1 = 1.f;
            #pragma unroll
            for (int nt = 0; nt < 8; nt++) { s[nt][2] = 0.f; s[nt][3] = 0.f; }
        } else {
            al1 = expf(m1 - mn1);
            #pragma unroll
            for (int nt = 0; nt < 8; nt++) {
                float p2 = expf(s[nt][2] - mn1), p3 = expf(s[nt][3] - mn1);
                s[nt][2] = p2; s[nt][3] = p3; ps1 += p2 + p3;
            }
        }
        ps0 += __shfl_xor_sync(0xffffffffu, ps0, 1);
        ps0 += __shfl_xor_sync(0xffffffffu, ps0, 2);
        ps1 += __shfl_xor_sync(0xffffffffu, ps1, 1);
        ps1 += __shfl_xor_sync(0xffffffffu, ps1, 2);
        l0 = l0 * al0 + ps0; m0 = mn0;
        l1 = l1 * al1 + ps1; m1 = mn1;
        #pragma unroll
        for (int dt = 0; dt < 8; dt++) {
            o[dt][0] *= al0; o[dt][1] *= al0;
            o[dt][2] *= al1; o[dt][3] *= al1;
        }

        #pragma unroll
        for (int ki = 0; ki < 4; ki++) {
            unsigned a0 = packh2(s[2*ki  ][0], s[2*ki  ][1]);
            unsigned a1 = packh2(s[2*ki  ][2], s[2*ki  ][3]);
            unsigned a2 = packh2(s[2*ki+1][0], s[2*ki+1][1]);
            unsigned a3 = packh2(s[2*ki+1][2], s[2*ki+1][3]);
            #pragma unroll
            for (int dt = 0; dt < 8; dt++) {
                unsigned b0, b1;
                unsigned vd = vbase + 2*((ki*16 + l15)*HSK + dt*8);
                LDSM_X2T(b0, b1, vd);
                MMA16816(o[dt][0], o[dt][1], o[dt][2], o[dt][3],
                         a0, a1, a2, a3, b0, b1);
            }
        }
    }

    float il0 = (l0 > 0.f) ? 1.f/l0 : 0.f;
    float il1 = (l1 > 0.f) ? 1.f/l1 : 0.f;
    size_t r0 = (size_t)(b*SEQ + q0 + w*16 + g) * EMBED + h*HDIM;
    size_t r1 = r0 + (size_t)8 * EMBED;
    #pragma unroll
    for (int dt = 0; dt < 8; dt++) {
        int cc = dt*8 + 2*t;
        *(unsigned*)(g_attn_h + r0 + cc) = packh2(o[dt][0]*il0, o[dt][1]*il0);
        *(unsigned*)(g_attn_h + r1 + cc) = packh2(o[dt][2]*il1, o[dt][3]*il1);
    }
}

// ---------------- swiglu: fp16 in (g_h_h), fp16 out (g_hg_h) --------------
__global__ void swiglu_kernel() {
    int idx = blockIdx.x * blockDim.x + threadIdx.x;
    int row = idx >> 10;
    int c4  = (idx & 1023) * 4;
    const __half* base = g_h_h + (size_t)row * (2*MLPD);
    uint2 au = *(const uint2*)(base + c4);
    uint2 gu = *(const uint2*)(base + MLPD + c4);
    float2 a01 = __half22float2(*reinterpret_cast<__half2*>(&au.x));
    float2 a23 = __half22float2(*reinterpret_cast<__half2*>(&au.y));
    float2 g01 = __half22float2(*reinterpret_cast<__half2*>(&gu.x));
    float2 g23 = __half22float2(*reinterpret_cast<__half2*>(&gu.y));
    float ox = a01.x / (1.f + expf(-a01.x)) * g01.x;
    float oy = a01.y / (1.f + expf(-a01.y)) * g01.y;
    float oz = a23.x / (1.f + expf(-a23.x)) * g23.x;
    float ow = a23.y / (1.f + expf(-a23.y)) * g23.y;
    *(uint2*)(g_hg_h + (size_t)row * MLPD + c4) = make_uint2(packh2(ox, oy), packh2(oz, ow));
}

// ------------------------------ launch ------------------------------------
static const int SIG_DECL[15] = {4194304,2048,4096,1024,1048576,1024,1048576,1024,
                                3145728,1048576,1024,8388608,8192,4194304,1024};
static const int SIG_ALPHA[15] = {4096,2048,8192,1024,8388608,4194304,1024,1024,
                                  1048576,3145728,1024,1048576,1024,1048576,4194304};
static const int MAP_ALPHA[15] = {14,1,0,6,11,10,13,12,9,8,7,4,2,5,3};

extern "C" void kernel_launch(void* const* d_in, const int* in_sizes, int n_in,
                              void* d_out, int out_size) {
    const void* in[15];
    bool decl_ok = (n_in >= 15), alpha_ok = (n_in >= 15);
    for (int i = 0; i < 15 && i < n_in; i++) {
        if (in_sizes[i] != SIG_DECL[i])  decl_ok = false;
        if (in_sizes[i] != SIG_ALPHA[i]) alpha_ok = false;
    }
    if (!decl_ok && alpha_ok) {
        for (int r = 0; r < 15; r++) in[r] = d_in[MAP_ALPHA[r]];
    } else {
        for (int r = 0; r < 15; r++) in[r] = d_in[r];
    }

    const float* x      = (const float*)in[0];
    const float* c      = (const float*)in[1];
    const int*   amask  = (const int*)  in[2];
    const float* norm_w = (const float*)in[3];
    const float* scale_w= (const float*)in[4];
    const float* scale_b= (const float*)in[5];
    const float* shift_w= (const float*)in[6];
    const float* shift_b= (const float*)in[7];
    const float* qkv_w  = (const float*)in[8];
    const float* proj_w = (const float*)in[9];
    const float* proj_b = (const float*)in[10];
    const float* mlp_w1 = (const float*)in[11];
    const float* mlp_b1 = (const float*)in[12];
    const float* mlp_w2 = (const float*)in[13];
    const float* mlp_b2 = (const float*)in[14];
    float* out = (float*)d_out;

    static bool attr_done = false;
    if (!attr_done) {
        cudaFuncSetAttribute(hgemm_kernel<0,0,false,false,false>,
                             cudaFuncAttributeMaxDynamicSharedMemorySize, TGEMM_SMEM);
        cudaFuncSetAttribute(hgemm_kernel<1,1,true,true,false>,
                             cudaFuncAttributeMaxDynamicSharedMemorySize, TGEMM_SMEM);
        cudaFuncSetAttribute(hgemm_kernel<0,2,true,false,false>,
                             cudaFuncAttributeMaxDynamicSharedMemorySize, TGEMM_SMEM);
        cudaFuncSetAttribute(hgemm_kernel<2,3,true,false,true>,
                             cudaFuncAttributeMaxDynamicSharedMemorySize, TGEMM_SMEM);
        attr_done = true;
    }

    // weight conversions (every launch; deterministic)
    cvtw_kernel<0><<<3*EMBED*EMBED/4/256, 256>>>((const float4*)qkv_w);
    cvtw_kernel<1><<<EMBED*EMBED/4/256, 256>>>((const float4*)proj_w);
    cvtw_kernel<2><<<2*MLPD*EMBED/4/256, 256>>>((const float4*)mlp_w1);
    cvtw_kernel<3><<<EMBED*MLPD/4/256, 256>>>((const float4*)mlp_w2);

    modvec_kernel<<<512, 256>>>(c, shift_w, shift_b, scale_w, scale_b);
    adaln_kernel<0><<<ROWS, 256>>>(x, norm_w);
    hgemm_kernel<0,0,false,false,false><<<dim3(3*EMBED/128, ROWS/128), 256, TGEMM_SMEM>>>(
        nullptr, nullptr, nullptr, ROWS, 3*EMBED, EMBED);
    attn_kernel<<<dim3(SEQ/64, HEADS, BATCH), 128>>>(amask);
    hgemm_kernel<1,1,true,true,false><<<dim3(EMBED/128, ROWS/128), 256, TGEMM_SMEM>>>(
        proj_b, x, nullptr, ROWS, EMBED, EMBED);
    adaln_kernel<1><<<ROWS, 256>>>(nullptr, norm_w);
    hgemm_kernel<0,2,true,false,false><<<dim3(2*MLPD/128, ROWS/128), 256, TGEMM_SMEM>>>(
        mlp_b1, nullptr, nullptr, ROWS, 2*MLPD, EMBED);
    swiglu_kernel<<<ROWS*(MLPD/4)/256, 256>>>();
    hgemm_kernel<2,3,true,false,true><<<dim3(EMBED/128, ROWS/128), 256, TGEMM_SMEM>>>(
        mlp_b2, nullptr, out, ROWS, EMBED, MLPD);
}